// round 1
// baseline (speedup 1.0000x reference)
#include <cuda_runtime.h>
#include <math.h>

#define Bc   2
#define Hc   32
#define Sc   1024
#define Dc   128
#define NBc  4
#define HIDc 4096
#define LOc  512
#define Mc   (Bc*Sc)        // 2048 rows

// ---------------- device scratch (no runtime allocation allowed) ------------
__device__ float g_U[2][(size_t)Mc * LOc];              // rank-512 intermediates (q,k)
__device__ float g_P[2][(size_t)Bc * Hc * Sc * Dc];     // projected q,k  [B,H,S,D]
__device__ float g_w[(size_t)Bc * Hc * Sc * NBc];       // alpha*blockscore/ (Z*cnt)
__device__ int   g_blk[Bc * Sc];                        // block id per (b,k)
__device__ float g_cnt[Bc * Sc * NBc];                  // causal-valid counts per (b,q,n)

// ---------------- prep: block ids + causal counts ---------------------------
__global__ void prep_kernel(const float* __restrict__ bmask) {
    int b = blockIdx.x;
    __shared__ int sblk[Sc];
    for (int k = threadIdx.x; k < Sc; k += blockDim.x) {
        int n = 0;
        for (int j = NBc - 1; j >= 0; --j)
            if (bmask[(b * NBc + j) * Sc + k] > 0.5f) n = j;
        sblk[k] = n;
        g_blk[b * Sc + k] = n;
    }
    __syncthreads();
    for (int q = threadIdx.x; q < Sc; q += blockDim.x) {
        int c0 = 0, c1 = 0, c2 = 0, c3 = 0;
        for (int k = 0; k <= q; ++k) {
            int n = sblk[k];
            c0 += (n == 0); c1 += (n == 1); c2 += (n == 2); c3 += (n == 3);
        }
        float* dst = &g_cnt[(b * Sc + q) * NBc];
        dst[0] = (float)c0; dst[1] = (float)c1; dst[2] = (float)c2; dst[3] = (float)c3;
    }
}

// ---------------- GEMM1: U[2048,512] = X(gathered)[2048,4096] * Wa^T --------
// X logical [m, c]: m=b*S+s, c=h*D+d -> query[((b*H+h)*S+s)*D+d]
__global__ void gemm1_kernel(const float* __restrict__ X,
                             const float* __restrict__ Wa, int which) {
    __shared__ float Xs[16][68];
    __shared__ float Ws[16][68];
    float* U = g_U[which];
    int n0 = blockIdx.x * 64;
    int m0 = blockIdx.y * 64;
    int tid = threadIdx.x;
    int tx = tid & 15, ty = tid >> 4;
    int lr = tid >> 2;          // 0..63
    int lc = (tid & 3) * 4;     // 0,4,8,12

    float acc[4][4];
#pragma unroll
    for (int i = 0; i < 4; ++i)
#pragma unroll
        for (int j = 0; j < 4; ++j) acc[i][j] = 0.f;

    for (int kt = 0; kt < HIDc / 16; ++kt) {
        {
            int m = m0 + lr;
            int gk = kt * 16 + lc;
            int b = m >> 10, s = m & 1023;
            int h = gk >> 7, d = gk & 127;
            const float4 v = *(const float4*)(X + (((size_t)(b * Hc + h)) * Sc + s) * Dc + d);
            Xs[lc + 0][lr] = v.x; Xs[lc + 1][lr] = v.y;
            Xs[lc + 2][lr] = v.z; Xs[lc + 3][lr] = v.w;
            int n = n0 + lr;
            const float4 w = *(const float4*)(Wa + (size_t)n * HIDc + kt * 16 + lc);
            Ws[lc + 0][lr] = w.x; Ws[lc + 1][lr] = w.y;
            Ws[lc + 2][lr] = w.z; Ws[lc + 3][lr] = w.w;
        }
        __syncthreads();
#pragma unroll
        for (int k = 0; k < 16; ++k) {
            float4 a = *(const float4*)&Xs[k][ty * 4];
            float4 bb = *(const float4*)&Ws[k][tx * 4];
            float av[4] = {a.x, a.y, a.z, a.w};
            float bv[4] = {bb.x, bb.y, bb.z, bb.w};
#pragma unroll
            for (int i = 0; i < 4; ++i)
#pragma unroll
                for (int j = 0; j < 4; ++j) acc[i][j] += av[i] * bv[j];
        }
        __syncthreads();
    }
#pragma unroll
    for (int i = 0; i < 4; ++i) {
        float4 o = make_float4(acc[i][0], acc[i][1], acc[i][2], acc[i][3]);
        *(float4*)(U + (size_t)(m0 + ty * 4 + i) * LOc + n0 + tx * 4) = o;
    }
}

// ---------------- GEMM2: P[b,h,s,d] = U[2048,512] * Wb^T (scattered) --------
__global__ void gemm2_kernel(const float* __restrict__ Wb, int which) {
    __shared__ float Us[16][68];
    __shared__ float Ws[16][68];
    const float* U = g_U[which];
    float* P = g_P[which];
    int n0 = blockIdx.x * 64;   // over 4096
    int m0 = blockIdx.y * 64;
    int tid = threadIdx.x;
    int tx = tid & 15, ty = tid >> 4;
    int lr = tid >> 2;
    int lc = (tid & 3) * 4;

    float acc[4][4];
#pragma unroll
    for (int i = 0; i < 4; ++i)
#pragma unroll
        for (int j = 0; j < 4; ++j) acc[i][j] = 0.f;

    for (int kt = 0; kt < LOc / 16; ++kt) {
        {
            const float4 v = *(const float4*)(U + (size_t)(m0 + lr) * LOc + kt * 16 + lc);
            Us[lc + 0][lr] = v.x; Us[lc + 1][lr] = v.y;
            Us[lc + 2][lr] = v.z; Us[lc + 3][lr] = v.w;
            const float4 w = *(const float4*)(Wb + (size_t)(n0 + lr) * LOc + kt * 16 + lc);
            Ws[lc + 0][lr] = w.x; Ws[lc + 1][lr] = w.y;
            Ws[lc + 2][lr] = w.z; Ws[lc + 3][lr] = w.w;
        }
        __syncthreads();
#pragma unroll
        for (int k = 0; k < 16; ++k) {
            float4 a = *(const float4*)&Us[k][ty * 4];
            float4 bb = *(const float4*)&Ws[k][tx * 4];
            float av[4] = {a.x, a.y, a.z, a.w};
            float bv[4] = {bb.x, bb.y, bb.z, bb.w};
#pragma unroll
            for (int i = 0; i < 4; ++i)
#pragma unroll
                for (int j = 0; j < 4; ++j) acc[i][j] += av[i] * bv[j];
        }
        __syncthreads();
    }
    int n = n0 + tx * 4;
    int h = n >> 7, d = n & 127;
#pragma unroll
    for (int i = 0; i < 4; ++i) {
        int m = m0 + ty * 4 + i;
        int b = m >> 10, s = m & 1023;
        float4 o = make_float4(acc[i][0], acc[i][1], acc[i][2], acc[i][3]);
        *(float4*)(P + (((size_t)(b * Hc + h)) * Sc + s) * Dc + d) = o;
    }
}

// ---------------- fused scores + softmax + block pooling --------------------
// grid: (16 q-tiles, B*H). block 256. Emits g_w[b,h,q,n] = alpha*sum_n/(Z*max(cnt,1))
#define SMEM_ATTN (2 * 128 * 68 * 4)
__global__ void attn_kernel(const float* __restrict__ alpha_p) {
    extern __shared__ float sm[];
    float* Qs = sm;               // [128][68] transposed q tile
    float* Ks = sm + 128 * 68;    // [128][68] transposed k tile
    __shared__ int sblk[64];

    int qt = 15 - blockIdx.x;     // heavy tiles launch first
    int bh = blockIdx.y;
    int b = bh >> 5;
    int q0 = qt * 64;
    int tid = threadIdx.x;
    int tx = tid & 15, ty = tid >> 4;

    const float* Qp = g_P[0] + (size_t)bh * Sc * Dc;
    const float* Kp = g_P[1] + (size_t)bh * Sc * Dc;

    for (int idx = tid; idx < 64 * 32; idx += 256) {
        int r = idx >> 5;
        int dv = (idx & 31) * 4;
        float4 v = *(const float4*)(Qp + (size_t)(q0 + r) * Dc + dv);
        Qs[(dv + 0) * 68 + r] = v.x; Qs[(dv + 1) * 68 + r] = v.y;
        Qs[(dv + 2) * 68 + r] = v.z; Qs[(dv + 3) * 68 + r] = v.w;
    }

    float m_run[4];
    float acc[4][NBc];
#pragma unroll
    for (int i = 0; i < 4; ++i) {
        m_run[i] = -1e30f;
#pragma unroll
        for (int n = 0; n < NBc; ++n) acc[i][n] = 0.f;
    }
    const float scaling = 0.08838834764831843f;   // 1/sqrt(128)

    for (int kt = 0; kt <= qt; ++kt) {
        int k0 = kt * 64;
        __syncthreads();
        for (int idx = tid; idx < 64 * 32; idx += 256) {
            int r = idx >> 5;
            int dv = (idx & 31) * 4;
            float4 v = *(const float4*)(Kp + (size_t)(k0 + r) * Dc + dv);
            Ks[(dv + 0) * 68 + r] = v.x; Ks[(dv + 1) * 68 + r] = v.y;
            Ks[(dv + 2) * 68 + r] = v.z; Ks[(dv + 3) * 68 + r] = v.w;
        }
        if (tid < 64) sblk[tid] = g_blk[b * Sc + k0 + tid];
        __syncthreads();

        float s[4][4];
#pragma unroll
        for (int i = 0; i < 4; ++i)
#pragma unroll
            for (int j = 0; j < 4; ++j) s[i][j] = 0.f;

#pragma unroll 16
        for (int d = 0; d < 128; ++d) {
            float4 a = *(const float4*)&Qs[d * 68 + ty * 4];
            float4 bb = *(const float4*)&Ks[d * 68 + tx * 4];
            float av[4] = {a.x, a.y, a.z, a.w};
            float bv[4] = {bb.x, bb.y, bb.z, bb.w};
#pragma unroll
            for (int i = 0; i < 4; ++i)
#pragma unroll
                for (int j = 0; j < 4; ++j) s[i][j] += av[i] * bv[j];
        }

        float tmax[4];
#pragma unroll
        for (int i = 0; i < 4; ++i) {
            int q = q0 + ty * 4 + i;
            float rmax = -1e30f;
#pragma unroll
            for (int j = 0; j < 4; ++j) {
                int k = k0 + tx * 4 + j;
                float v = s[i][j] * scaling;
                if (k > q) v = -1e30f;      // causal mask (only on diagonal tile)
                s[i][j] = v;
                rmax = fmaxf(rmax, v);
            }
            tmax[i] = rmax;
        }
#pragma unroll
        for (int off = 8; off >= 1; off >>= 1)
#pragma unroll
            for (int i = 0; i < 4; ++i)
                tmax[i] = fmaxf(tmax[i], __shfl_xor_sync(0xffffffffu, tmax[i], off, 32));

        int bj0 = sblk[tx * 4 + 0], bj1 = sblk[tx * 4 + 1];
        int bj2 = sblk[tx * 4 + 2], bj3 = sblk[tx * 4 + 3];
#pragma unroll
        for (int i = 0; i < 4; ++i) {
            float nm = fmaxf(m_run[i], tmax[i]);
            float sc = __expf(m_run[i] - nm);
            m_run[i] = nm;
#pragma unroll
            for (int n = 0; n < NBc; ++n) acc[i][n] *= sc;
            float e0 = __expf(s[i][0] - nm);
            float e1 = __expf(s[i][1] - nm);
            float e2 = __expf(s[i][2] - nm);
            float e3 = __expf(s[i][3] - nm);
#pragma unroll
            for (int n = 0; n < NBc; ++n) {
                float add = 0.f;
                add += (bj0 == n) ? e0 : 0.f;
                add += (bj1 == n) ? e1 : 0.f;
                add += (bj2 == n) ? e2 : 0.f;
                add += (bj3 == n) ? e3 : 0.f;
                acc[i][n] += add;
            }
        }
    }

    // reduce block sums across the 16 column-threads of each row
#pragma unroll
    for (int off = 8; off >= 1; off >>= 1)
#pragma unroll
        for (int i = 0; i < 4; ++i)
#pragma unroll
            for (int n = 0; n < NBc; ++n)
                acc[i][n] += __shfl_xor_sync(0xffffffffu, acc[i][n], off, 32);

    if (tx == 0) {
        float alpha = *alpha_p;
#pragma unroll
        for (int i = 0; i < 4; ++i) {
            int q = q0 + ty * 4 + i;
            float Z = acc[i][0] + acc[i][1] + acc[i][2] + acc[i][3];
            float inv = alpha / Z;
            const float* cnt = &g_cnt[(b * Sc + q) * NBc];
            float* dst = &g_w[((size_t)bh * Sc + q) * NBc];
#pragma unroll
            for (int n = 0; n < NBc; ++n)
                dst[n] = acc[i][n] * inv / fmaxf(cnt[n], 1.f);
        }
    }
}

// ---------------- expand: out[b,h,q,k] = (k<=q) ? w[b,h,q,blk(b,k)] : 0 -----
__global__ void expand_kernel(float* __restrict__ out) {
    int row = blockIdx.x;           // bh*1024 + q
    int q = row & (Sc - 1);
    int bh = row >> 10;
    int b = bh >> 5;
    __shared__ float4 w4s;
    if (threadIdx.x == 0) w4s = *(const float4*)&g_w[(size_t)row * NBc];
    __syncthreads();
    float w0 = w4s.x, w1 = w4s.y, w2 = w4s.z, w3 = w4s.w;
    int k = threadIdx.x * 4;
    int4 bl = *(const int4*)&g_blk[b * Sc + k];
    float4 o;
    o.x = (k + 0 <= q) ? (bl.x == 0 ? w0 : bl.x == 1 ? w1 : bl.x == 2 ? w2 : w3) : 0.f;
    o.y = (k + 1 <= q) ? (bl.y == 0 ? w0 : bl.y == 1 ? w1 : bl.y == 2 ? w2 : w3) : 0.f;
    o.z = (k + 2 <= q) ? (bl.z == 0 ? w0 : bl.z == 1 ? w1 : bl.z == 2 ? w2 : w3) : 0.f;
    o.w = (k + 3 <= q) ? (bl.w == 0 ? w0 : bl.w == 1 ? w1 : bl.w == 2 ? w2 : w3) : 0.f;
    *(float4*)(out + (size_t)row * Sc + k) = o;
}

// ---------------- launch -----------------------------------------------------
extern "C" void kernel_launch(void* const* d_in, const int* in_sizes, int n_in,
                              void* d_out, int out_size) {
    const float* query = (const float*)d_in[0];
    const float* key   = (const float*)d_in[1];
    const float* Wqa   = (const float*)d_in[2];
    const float* Wqb   = (const float*)d_in[3];
    const float* Wka   = (const float*)d_in[4];
    const float* Wkb   = (const float*)d_in[5];
    const float* alpha = (const float*)d_in[6];
    const float* bmask = (const float*)d_in[7];
    // d_in[8] = attention_mask: deterministic causal, handled analytically
    float* out = (float*)d_out;

    prep_kernel<<<Bc, 256>>>(bmask);

    gemm1_kernel<<<dim3(LOc / 64, Mc / 64), 256>>>(query, Wqa, 0);
    gemm1_kernel<<<dim3(LOc / 64, Mc / 64), 256>>>(key,   Wka, 1);
    gemm2_kernel<<<dim3(HIDc / 64, Mc / 64), 256>>>(Wqb, 0);
    gemm2_kernel<<<dim3(HIDc / 64, Mc / 64), 256>>>(Wkb, 1);

    static bool attr_set = false;
    cudaFuncSetAttribute(attn_kernel, cudaFuncAttributeMaxDynamicSharedMemorySize, SMEM_ATTN);
    (void)attr_set;
    attn_kernel<<<dim3(16, Bc * Hc), 256, SMEM_ATTN>>>(alpha);

    expand_kernel<<<Bc * Hc * Sc, 256>>>(out);
}

// round 2
// speedup vs baseline: 2.5384x; 2.5384x over previous
#include <cuda_runtime.h>
#include <cuda_fp16.h>
#include <math.h>
#include <stdint.h>

#define Bc   2
#define Hc   32
#define Sc   1024
#define Dc   128
#define NBc  4
#define HIDc 4096
#define LOc  512
#define Mc   (Bc*Sc)        // 2048 rows

// ---------------- device scratch ---------------------------------------------
__device__ float g_U[4][(size_t)Mc * LOc];              // splitK halves: q0,q1,k0,k1
__device__ float g_P[2][(size_t)Bc * Hc * Sc * Dc];     // projected q,k [B,H,S,D]
__device__ float g_w[(size_t)Bc * Hc * Sc * NBc];       // alpha*blockscore/(Z*cnt)
__device__ int   g_blk[Bc * Sc];
__device__ float g_cnt[Bc * Sc * NBc];

// ---------------- PTX helpers -------------------------------------------------
__device__ __forceinline__ uint32_t sptr(const void* p) {
    return (uint32_t)__cvta_generic_to_shared(p);
}

#define LDSM4(r, addr) asm volatile( \
    "ldmatrix.sync.aligned.m8n8.x4.shared.b16 {%0,%1,%2,%3}, [%4];" \
    : "=r"((r)[0]), "=r"((r)[1]), "=r"((r)[2]), "=r"((r)[3]) : "r"(addr))

#define MMA16816(c, a, b0, b1) asm volatile( \
    "mma.sync.aligned.m16n8k16.row.col.f32.f16.f16.f32 " \
    "{%0,%1,%2,%3},{%4,%5,%6,%7},{%8,%9},{%0,%1,%2,%3};" \
    : "+f"((c)[0]), "+f"((c)[1]), "+f"((c)[2]), "+f"((c)[3]) \
    : "r"((a)[0]), "r"((a)[1]), "r"((a)[2]), "r"((a)[3]), "r"(b0), "r"(b1))

// fast exp: FMA-pipe only (no MUFU). rel err ~3e-6.
__device__ __forceinline__ float fexp(float x) {
    float t = fmaxf(x * 1.4426950408889634f, -120.f);
    float r = t + 12582912.f;                 // round-to-nearest via magic
    int   i = __float_as_int(r) - 0x4B400000;
    float f = t - (r - 12582912.f);           // f in [-0.5, 0.5]
    float p = 1.3333558e-3f;                  // 2^f poly (deg 5)
    p = fmaf(p, f, 9.6181291e-3f);
    p = fmaf(p, f, 5.5504109e-2f);
    p = fmaf(p, f, 2.4022651e-1f);
    p = fmaf(p, f, 6.9314718e-1f);
    p = fmaf(p, f, 1.0f);
    return __int_as_float(__float_as_int(p) + (i << 23));
}

__device__ __forceinline__ void cvt_store4(__half* hi, __half* lo, float4 v) {
    __half h0 = __float2half_rn(v.x), h1 = __float2half_rn(v.y);
    __half h2 = __float2half_rn(v.z), h3 = __float2half_rn(v.w);
    __half l0 = __float2half_rn(v.x - __half2float(h0));
    __half l1 = __float2half_rn(v.y - __half2float(h1));
    __half l2 = __float2half_rn(v.z - __half2float(h2));
    __half l3 = __float2half_rn(v.w - __half2float(h3));
    *(__half2*)(hi)     = __halves2half2(h0, h1);
    *(__half2*)(hi + 2) = __halves2half2(h2, h3);
    *(__half2*)(lo)     = __halves2half2(l0, l1);
    *(__half2*)(lo + 2) = __halves2half2(l2, l3);
}

// ---------------- prep: block ids + causal counts ----------------------------
__global__ void prep_kernel(const float* __restrict__ bmask) {
    int b = blockIdx.x;
    __shared__ int sblk[Sc];
    for (int k = threadIdx.x; k < Sc; k += blockDim.x) {
        int n = 0;
        for (int j = NBc - 1; j >= 0; --j)
            if (bmask[(b * NBc + j) * Sc + k] > 0.5f) n = j;
        sblk[k] = n;
        g_blk[b * Sc + k] = n;
    }
    __syncthreads();
    for (int q = threadIdx.x; q < Sc; q += blockDim.x) {
        int c0 = 0, c1 = 0, c2 = 0, c3 = 0;
        for (int k = 0; k <= q; ++k) {
            int n = sblk[k];
            c0 += (n == 0); c1 += (n == 1); c2 += (n == 2); c3 += (n == 3);
        }
        float* dst = &g_cnt[(b * Sc + q) * NBc];
        dst[0] = (float)c0; dst[1] = (float)c1; dst[2] = (float)c2; dst[3] = (float)c3;
    }
}

// ---------------- GEMM1 (tensor, split-fp16 x3, splitK=2) --------------------
// U[z][2048,512] partial = X(gathered)[2048, k in half] * Wa^T
__global__ __launch_bounds__(256, 1) void gemm1_tc(
    const float* __restrict__ Xq, const float* __restrict__ Xk,
    const float* __restrict__ Wqa, const float* __restrict__ Wka) {
    const int BN = 64;
    __shared__ __half Ah[128][40], Al[128][40], Bh[BN][40], Bl[BN][40];
    int z = blockIdx.z;                       // bit1: q/k, bit0: K split
    const float* X = (z & 2) ? Xk : Xq;
    const float* W = (z & 2) ? Wka : Wqa;
    float* U = g_U[z];
    int kbase = (z & 1) * 2048;
    int n0 = blockIdx.x * BN;
    int m0 = blockIdx.y * 128;
    int tid = threadIdx.x;
    int lane = tid & 31, warp = tid >> 5;
    int wm = (warp & 3) * 32;
    int wn = (warp >> 2) * (BN / 2);
    int arow = tid >> 3, acol = (tid & 7) * 4;

    float acc[2][4][4];
#pragma unroll
    for (int i = 0; i < 2; ++i)
#pragma unroll
        for (int j = 0; j < 4; ++j)
#pragma unroll
            for (int l = 0; l < 4; ++l) acc[i][j][l] = 0.f;

    for (int kb = 0; kb < 2048; kb += 32) {
        __syncthreads();
#pragma unroll
        for (int i = 0; i < 4; ++i) {
            int row = arow + i * 32;
            int m = m0 + row;
            int k = kbase + kb + acol;
            const float4 v = *(const float4*)(X +
                (((size_t)((m >> 10) * Hc + (k >> 7))) * Sc + (m & 1023)) * Dc + (k & 127));
            cvt_store4(&Ah[row][acol], &Al[row][acol], v);
        }
#pragma unroll
        for (int i = 0; i < BN / 32; ++i) {
            int row = arow + i * 32;
            const float4 v = *(const float4*)(W + (size_t)(n0 + row) * HIDc + kbase + kb + acol);
            cvt_store4(&Bh[row][acol], &Bl[row][acol], v);
        }
        __syncthreads();
#pragma unroll
        for (int ks = 0; ks < 2; ++ks) {
            uint32_t ah[2][4], al[2][4];
#pragma unroll
            for (int mf = 0; mf < 2; ++mf) {
                int r = wm + mf * 16 + (lane & 15);
                int c = ks * 16 + 8 * (lane >> 4);
                LDSM4(ah[mf], sptr(&Ah[r][c]));
                LDSM4(al[mf], sptr(&Al[r][c]));
            }
            uint32_t bh[2][4], bl[2][4];
#pragma unroll
            for (int p = 0; p < 2; ++p) {
                int r = wn + p * 16 + (lane & 7) + ((lane & 16) >> 1);
                int c = ks * 16 + (lane & 8);
                LDSM4(bh[p], sptr(&Bh[r][c]));
                LDSM4(bl[p], sptr(&Bl[r][c]));
            }
#pragma unroll
            for (int mf = 0; mf < 2; ++mf)
#pragma unroll
                for (int nt = 0; nt < 4; ++nt) {
                    uint32_t* bhp = &bh[nt >> 1][(nt & 1) * 2];
                    uint32_t* blp = &bl[nt >> 1][(nt & 1) * 2];
                    MMA16816(acc[mf][nt], ah[mf], bhp[0], bhp[1]);
                    MMA16816(acc[mf][nt], ah[mf], blp[0], blp[1]);
                    MMA16816(acc[mf][nt], al[mf], bhp[0], bhp[1]);
                }
        }
    }
#pragma unroll
    for (int mf = 0; mf < 2; ++mf)
#pragma unroll
        for (int nt = 0; nt < 4; ++nt) {
            int r = m0 + wm + mf * 16 + (lane >> 2);
            int c = n0 + wn + nt * 8 + (lane & 3) * 2;
            *(float2*)&U[(size_t)r * LOc + c]       = make_float2(acc[mf][nt][0], acc[mf][nt][1]);
            *(float2*)&U[(size_t)(r + 8) * LOc + c] = make_float2(acc[mf][nt][2], acc[mf][nt][3]);
        }
}

// ---------------- GEMM2 (tensor, split-fp16 x3; A = U0+U1; scatter out) ------
__global__ __launch_bounds__(256, 1) void gemm2_tc(
    const float* __restrict__ Wqb, const float* __restrict__ Wkb) {
    __shared__ __half Ah[128][40], Al[128][40], Bh[128][40], Bl[128][40];
    int z = blockIdx.z;                       // 0=q, 1=k
    const float* U0 = g_U[2 * z];
    const float* U1 = g_U[2 * z + 1];
    const float* W = z ? Wkb : Wqb;
    float* P = g_P[z];
    int n0 = blockIdx.x * 128;
    int m0 = blockIdx.y * 128;
    int tid = threadIdx.x;
    int lane = tid & 31, warp = tid >> 5;
    int wm = (warp & 3) * 32;
    int wn = (warp >> 2) * 64;
    int arow = tid >> 3, acol = (tid & 7) * 4;

    float acc[2][8][4];
#pragma unroll
    for (int i = 0; i < 2; ++i)
#pragma unroll
        for (int j = 0; j < 8; ++j)
#pragma unroll
            for (int l = 0; l < 4; ++l) acc[i][j][l] = 0.f;

    for (int kb = 0; kb < LOc; kb += 32) {
        __syncthreads();
#pragma unroll
        for (int i = 0; i < 4; ++i) {
            int row = arow + i * 32;
            size_t off = (size_t)(m0 + row) * LOc + kb + acol;
            float4 v  = *(const float4*)(U0 + off);
            float4 v2 = *(const float4*)(U1 + off);
            v.x += v2.x; v.y += v2.y; v.z += v2.z; v.w += v2.w;
            cvt_store4(&Ah[row][acol], &Al[row][acol], v);
        }
#pragma unroll
        for (int i = 0; i < 4; ++i) {
            int row = arow + i * 32;
            const float4 v = *(const float4*)(W + (size_t)(n0 + row) * LOc + kb + acol);
            cvt_store4(&Bh[row][acol], &Bl[row][acol], v);
        }
        __syncthreads();
#pragma unroll
        for (int ks = 0; ks < 2; ++ks) {
            uint32_t ah[2][4], al[2][4];
#pragma unroll
            for (int mf = 0; mf < 2; ++mf) {
                int r = wm + mf * 16 + (lane & 15);
                int c = ks * 16 + 8 * (lane >> 4);
                LDSM4(ah[mf], sptr(&Ah[r][c]));
                LDSM4(al[mf], sptr(&Al[r][c]));
            }
            uint32_t bh[4][4], bl[4][4];
#pragma unroll
            for (int p = 0; p < 4; ++p) {
                int r = wn + p * 16 + (lane & 7) + ((lane & 16) >> 1);
                int c = ks * 16 + (lane & 8);
                LDSM4(bh[p], sptr(&Bh[r][c]));
                LDSM4(bl[p], sptr(&Bl[r][c]));
            }
#pragma unroll
            for (int mf = 0; mf < 2; ++mf)
#pragma unroll
                for (int nt = 0; nt < 8; ++nt) {
                    uint32_t* bhp = &bh[nt >> 1][(nt & 1) * 2];
                    uint32_t* blp = &bl[nt >> 1][(nt & 1) * 2];
                    MMA16816(acc[mf][nt], ah[mf], bhp[0], bhp[1]);
                    MMA16816(acc[mf][nt], ah[mf], blp[0], blp[1]);
                    MMA16816(acc[mf][nt], al[mf], bhp[0], bhp[1]);
                }
        }
    }
#pragma unroll
    for (int mf = 0; mf < 2; ++mf)
#pragma unroll
        for (int nt = 0; nt < 8; ++nt) {
            int r = m0 + wm + mf * 16 + (lane >> 2);
            int c = n0 + wn + nt * 8 + (lane & 3) * 2;
            int h = c >> 7, d = c & 127;
            int bb = r >> 10, s = r & 1023;
            size_t base = (((size_t)(bb * Hc + h)) * Sc + s) * Dc + d;
            *(float2*)&P[base]            = make_float2(acc[mf][nt][0], acc[mf][nt][1]);
            *(float2*)&P[base + 8 * Dc]   = make_float2(acc[mf][nt][2], acc[mf][nt][3]);
        }
}

// ---------------- fused scores + softmax + block pooling (tensor) ------------
__global__ __launch_bounds__(128, 1) void attn_tc(const float* __restrict__ alpha_p) {
    __shared__ __half Qs[64][136];
    __shared__ __half Ks[64][136];
    __shared__ int sblk[64];

    int qt = 15 - blockIdx.x;
    int bh = blockIdx.y;
    int b = bh >> 5;
    int q0 = qt * 64;
    int tid = threadIdx.x;
    int lane = tid & 31, warp = tid >> 5;

    const float* Qp = g_P[0] + (size_t)bh * Sc * Dc;
    const float* Kp = g_P[1] + (size_t)bh * Sc * Dc;

    // load Q tile (fp16, no split)
    {
        int row = tid >> 1;
        int cb = (tid & 1) * 64;
#pragma unroll
        for (int j = 0; j < 16; ++j) {
            int col = cb + j * 4;
            float4 v = *(const float4*)(Qp + (size_t)(q0 + row) * Dc + col);
            *(__half2*)&Qs[row][col]     = __floats2half2_rn(v.x, v.y);
            *(__half2*)&Qs[row][col + 2] = __floats2half2_rn(v.z, v.w);
        }
    }

    float ab[2][4];
#pragma unroll
    for (int i = 0; i < 2; ++i)
#pragma unroll
        for (int n = 0; n < 4; ++n) ab[i][n] = 0.f;

    const float scaling = 0.08838834764831843f;
    int r0g = q0 + warp * 16 + (lane >> 2);

    for (int kt = 0; kt <= qt; ++kt) {
        int k0 = kt * 64;
        __syncthreads();
        {
            int row = tid >> 1;
            int cb = (tid & 1) * 64;
#pragma unroll
            for (int j = 0; j < 16; ++j) {
                int col = cb + j * 4;
                float4 v = *(const float4*)(Kp + (size_t)(k0 + row) * Dc + col);
                *(__half2*)&Ks[row][col]     = __floats2half2_rn(v.x, v.y);
                *(__half2*)&Ks[row][col + 2] = __floats2half2_rn(v.z, v.w);
            }
        }
        if (tid < 64) sblk[tid] = g_blk[b * Sc + k0 + tid];
        __syncthreads();

        float acc[8][4];
#pragma unroll
        for (int j = 0; j < 8; ++j)
#pragma unroll
            for (int l = 0; l < 4; ++l) acc[j][l] = 0.f;

#pragma unroll
        for (int ks = 0; ks < 8; ++ks) {
            uint32_t a[4];
            {
                int r = warp * 16 + (lane & 15);
                int c = ks * 16 + 8 * (lane >> 4);
                LDSM4(a, sptr(&Qs[r][c]));
            }
            uint32_t bfr[4][4];
#pragma unroll
            for (int p = 0; p < 4; ++p) {
                int r = p * 16 + (lane & 7) + ((lane & 16) >> 1);
                int c = ks * 16 + (lane & 8);
                LDSM4(bfr[p], sptr(&Ks[r][c]));
            }
#pragma unroll
            for (int nt = 0; nt < 8; ++nt) {
                uint32_t* bp = &bfr[nt >> 1][(nt & 1) * 2];
                MMA16816(acc[nt], a, bp[0], bp[1]);
            }
        }

        bool diag = (kt == qt);
#pragma unroll
        for (int nt = 0; nt < 8; ++nt) {
            int c0 = nt * 8 + (lane & 3) * 2;
            int blk0 = sblk[c0], blk1 = sblk[c0 + 1];
            int kc0 = k0 + c0;
            float e00 = fexp(acc[nt][0] * scaling);
            float e01 = fexp(acc[nt][1] * scaling);
            float e10 = fexp(acc[nt][2] * scaling);
            float e11 = fexp(acc[nt][3] * scaling);
            if (diag) {
                if (kc0 > r0g)     e00 = 0.f;
                if (kc0 + 1 > r0g) e01 = 0.f;
                if (kc0 > r0g + 8)     e10 = 0.f;
                if (kc0 + 1 > r0g + 8) e11 = 0.f;
            }
#pragma unroll
            for (int n = 0; n < 4; ++n) {
                ab[0][n] += (blk0 == n ? e00 : 0.f) + (blk1 == n ? e01 : 0.f);
                ab[1][n] += (blk0 == n ? e10 : 0.f) + (blk1 == n ? e11 : 0.f);
            }
        }
    }

    // reduce across the 4 lanes of each row-quad
#pragma unroll
    for (int off = 1; off <= 2; off <<= 1)
#pragma unroll
        for (int i = 0; i < 2; ++i)
#pragma unroll
            for (int n = 0; n < 4; ++n)
                ab[i][n] += __shfl_xor_sync(0xffffffffu, ab[i][n], off, 32);

    if ((lane & 3) == 0) {
        float alpha = *alpha_p;
#pragma unroll
        for (int i = 0; i < 2; ++i) {
            int r = r0g + i * 8;
            float Z = ab[i][0] + ab[i][1] + ab[i][2] + ab[i][3];
            float inv = alpha / Z;
            const float* cnt = &g_cnt[(b * Sc + r) * NBc];
            float* dst = &g_w[((size_t)bh * Sc + r) * NBc];
#pragma unroll
            for (int n = 0; n < NBc; ++n)
                dst[n] = ab[i][n] * inv / fmaxf(cnt[n], 1.f);
        }
    }
}

// ---------------- expand ------------------------------------------------------
__global__ void expand_kernel(float* __restrict__ out) {
    int row = blockIdx.x;
    int q = row & (Sc - 1);
    int bh = row >> 10;
    int b = bh >> 5;
    __shared__ float4 w4s;
    if (threadIdx.x == 0) w4s = *(const float4*)&g_w[(size_t)row * NBc];
    __syncthreads();
    float w0 = w4s.x, w1 = w4s.y, w2 = w4s.z, w3 = w4s.w;
    int k = threadIdx.x * 4;
    int4 bl = *(const int4*)&g_blk[b * Sc + k];
    float4 o;
    o.x = (k + 0 <= q) ? (bl.x == 0 ? w0 : bl.x == 1 ? w1 : bl.x == 2 ? w2 : w3) : 0.f;
    o.y = (k + 1 <= q) ? (bl.y == 0 ? w0 : bl.y == 1 ? w1 : bl.y == 2 ? w2 : w3) : 0.f;
    o.z = (k + 2 <= q) ? (bl.z == 0 ? w0 : bl.z == 1 ? w1 : bl.z == 2 ? w2 : w3) : 0.f;
    o.w = (k + 3 <= q) ? (bl.w == 0 ? w0 : bl.w == 1 ? w1 : bl.w == 2 ? w2 : w3) : 0.f;
    *(float4*)(out + (size_t)row * Sc + k) = o;
}

// ---------------- launch ------------------------------------------------------
extern "C" void kernel_launch(void* const* d_in, const int* in_sizes, int n_in,
                              void* d_out, int out_size) {
    const float* query = (const float*)d_in[0];
    const float* key   = (const float*)d_in[1];
    const float* Wqa   = (const float*)d_in[2];
    const float* Wqb   = (const float*)d_in[3];
    const float* Wka   = (const float*)d_in[4];
    const float* Wkb   = (const float*)d_in[5];
    const float* alpha = (const float*)d_in[6];
    const float* bmask = (const float*)d_in[7];
    float* out = (float*)d_out;

    prep_kernel<<<Bc, 256>>>(bmask);
    gemm1_tc<<<dim3(LOc / 64, Mc / 128, 4), 256>>>(query, key, Wqa, Wka);
    gemm2_tc<<<dim3(HIDc / 128, Mc / 128, 2), 256>>>(Wqb, Wkb);
    attn_tc<<<dim3(16, Bc * Hc), 128>>>(alpha);
    expand_kernel<<<Bc * Hc * Sc, 256>>>(out);
}

// round 4
// speedup vs baseline: 3.0294x; 1.1935x over previous
#include <cuda_runtime.h>
#include <cuda_fp16.h>
#include <math.h>
#include <stdint.h>

#define Bc   2
#define Hc   32
#define Sc   1024
#define Dc   128
#define NBc  4
#define HIDc 4096
#define LOc  512
#define Mc   (Bc*Sc)

// ---------------- device scratch ---------------------------------------------
__device__ __half g_Xh[2][(size_t)Mc * HIDc];
__device__ __half g_Xl[2][(size_t)Mc * HIDc];
__device__ __half g_Wah[2][(size_t)LOc * HIDc];
__device__ __half g_Wal[2][(size_t)LOc * HIDc];
__device__ __half g_Wbh[2][(size_t)HIDc * LOc];
__device__ __half g_Wbl[2][(size_t)HIDc * LOc];
__device__ float  g_U[4][(size_t)Mc * LOc];
__device__ __half g_Uh[2][(size_t)Mc * LOc];
__device__ __half g_Ul[2][(size_t)Mc * LOc];
__device__ __half g_Ph[2][(size_t)Bc * Hc * Sc * Dc];
__device__ float  g_w[(size_t)Bc * Hc * Sc * NBc];
__device__ int    g_blk[Bc * Sc];
__device__ int    g_tblk[Bc * 16];          // uniform block id per 64-tile, or -1
__device__ float  g_cnt[Bc * Sc * NBc];

// ---------------- PTX helpers -------------------------------------------------
__device__ __forceinline__ uint32_t sptr(const void* p) {
    return (uint32_t)__cvta_generic_to_shared(p);
}
#define LDSM4(r, addr) asm volatile( \
    "ldmatrix.sync.aligned.m8n8.x4.shared.b16 {%0,%1,%2,%3}, [%4];" \
    : "=r"((r)[0]), "=r"((r)[1]), "=r"((r)[2]), "=r"((r)[3]) : "r"(addr))
#define MMA16816(c, a, b0, b1) asm volatile( \
    "mma.sync.aligned.m16n8k16.row.col.f32.f16.f16.f32 " \
    "{%0,%1,%2,%3},{%4,%5,%6,%7},{%8,%9},{%0,%1,%2,%3};" \
    : "+f"((c)[0]), "+f"((c)[1]), "+f"((c)[2]), "+f"((c)[3]) \
    : "r"((a)[0]), "r"((a)[1]), "r"((a)[2]), "r"((a)[3]), "r"(b0), "r"(b1))
#define CP16(dst, src) asm volatile( \
    "cp.async.cg.shared.global [%0], [%1], 16;" :: "r"(dst), "l"(src))
#define CPCOMMIT() asm volatile("cp.async.commit_group;")
#define CPWAIT(N)  asm volatile("cp.async.wait_group %0;" :: "n"(N))

// base-2 exp with 1/sqrt(D)*log2(e) prefolded; FMA-pipe only
__device__ __forceinline__ float fexp2s(float x) {
    const float CS = 0.08838834764831843f * 1.4426950408889634f;
    float t = fmaxf(x * CS, -110.f);
    float r = t + 12582912.f;
    int   i = __float_as_int(r) - 0x4B400000;
    float f = t - (r - 12582912.f);
    float p = 1.3333558e-3f;
    p = fmaf(p, f, 9.6181291e-3f);
    p = fmaf(p, f, 5.5504109e-2f);
    p = fmaf(p, f, 2.4022651e-1f);
    p = fmaf(p, f, 6.9314718e-1f);
    p = fmaf(p, f, 1.0f);
    return __int_as_float(__float_as_int(p) + (i << 23));
}

__device__ __forceinline__ void split4(float4 v, __half* hi, __half* lo) {
    __half h0 = __float2half_rn(v.x), h1 = __float2half_rn(v.y);
    __half h2 = __float2half_rn(v.z), h3 = __float2half_rn(v.w);
    *(__half2*)(hi)     = __halves2half2(h0, h1);
    *(__half2*)(hi + 2) = __halves2half2(h2, h3);
    *(__half2*)(lo)     = __halves2half2(__float2half_rn(v.x - __half2float(h0)),
                                         __float2half_rn(v.y - __half2float(h1)));
    *(__half2*)(lo + 2) = __halves2half2(__float2half_rn(v.z - __half2float(h2)),
                                         __float2half_rn(v.w - __half2float(h3)));
}

// ---------------- prep ---------------------------------------------------------
__global__ void prep_kernel(const float* __restrict__ bmask) {
    int b = blockIdx.x;
    __shared__ int sblk[Sc];
    for (int k = threadIdx.x; k < Sc; k += blockDim.x) {
        int n = 0;
        for (int j = NBc - 1; j >= 0; --j)
            if (bmask[(b * NBc + j) * Sc + k] > 0.5f) n = j;
        sblk[k] = n;
        g_blk[b * Sc + k] = n;
    }
    __syncthreads();
    for (int q = threadIdx.x; q < Sc; q += blockDim.x) {
        int c0 = 0, c1 = 0, c2 = 0, c3 = 0;
        for (int k = 0; k <= q; ++k) {
            int n = sblk[k];
            c0 += (n == 0); c1 += (n == 1); c2 += (n == 2); c3 += (n == 3);
        }
        float* dst = &g_cnt[(b * Sc + q) * NBc];
        dst[0] = (float)c0; dst[1] = (float)c1; dst[2] = (float)c2; dst[3] = (float)c3;
    }
    if (threadIdx.x < 16) {
        int t = threadIdx.x;
        int u = sblk[t * 64];
        bool uni = true;
        for (int j = 1; j < 64; ++j) uni &= (sblk[t * 64 + j] == u);
        g_tblk[b * 16 + t] = uni ? u : -1;
    }
}

// ---------------- conversions --------------------------------------------------
__global__ void xsplit_kernel(const float* __restrict__ q, const float* __restrict__ k) {
    int z = blockIdx.y;
    const float* X = z ? k : q;
    __half* Hh = g_Xh[z];          // device-side address resolution (NOT host-passed)
    __half* Hl = g_Xl[z];
    size_t i4 = (size_t)blockIdx.x * blockDim.x + threadIdx.x;   // < 2048*1024
    int m = (int)(i4 >> 10);
    int c = (int)(i4 & 1023) * 4;
    int h = c >> 7, d = c & 127, b = m >> 10, s = m & 1023;
    float4 v = *(const float4*)(X + (((size_t)(b * Hc + h)) * Sc + s) * Dc + d);
    split4(v, Hh + i4 * 4, Hl + i4 * 4);
}

// sel: 0 = Wqa->Wa[0], 1 = Wka->Wa[1], 2 = Wqb->Wb[0], 3 = Wkb->Wb[1]
// CRITICAL: destination globals resolved in DEVICE code. Passing g_Wah[i] from
// host passes the host shadow address; on GB300 (ATS) the kernel then silently
// writes to HOST memory and the device arrays stay zero (round-3 bug).
__global__ void wsplit_kernel(const float* __restrict__ src, int sel) {
    __half* hi;
    __half* lo;
    switch (sel) {
        case 0:  hi = g_Wah[0]; lo = g_Wal[0]; break;
        case 1:  hi = g_Wah[1]; lo = g_Wal[1]; break;
        case 2:  hi = g_Wbh[0]; lo = g_Wbl[0]; break;
        default: hi = g_Wbh[1]; lo = g_Wbl[1]; break;
    }
    size_t i4 = (size_t)blockIdx.x * blockDim.x + threadIdx.x;   // < 524288
    float4 v = ((const float4*)src)[i4];
    split4(v, hi + i4 * 4, lo + i4 * 4);
}

__global__ void uconv_kernel() {
    int z = blockIdx.y;
    size_t i4 = (size_t)blockIdx.x * blockDim.x + threadIdx.x;   // < 262144
    float4 a = ((const float4*)g_U[2 * z])[i4];
    float4 b = ((const float4*)g_U[2 * z + 1])[i4];
    a.x += b.x; a.y += b.y; a.z += b.z; a.w += b.w;
    split4(a, g_Uh[z] + i4 * 4, g_Ul[z] + i4 * 4);
}

// ---------------- GEMM1: U = X * Wa^T (fp16 3-pass, splitK=2, cp.async) -------
__global__ __launch_bounds__(256) void gemm1_tc() {
    extern __shared__ __half sm[];
    __half* Ah = sm;                     // [2][128*40]
    __half* Al = Ah + 2 * 128 * 40;
    __half* Bh = Al + 2 * 128 * 40;      // [2][64*40]
    __half* Bl = Bh + 2 * 64 * 40;

    int z = blockIdx.z;                  // bit1: q/k, bit0: K-split
    const __half* Xh = g_Xh[z >> 1];
    const __half* Xl = g_Xl[z >> 1];
    const __half* Wh = g_Wah[z >> 1];
    const __half* Wl = g_Wal[z >> 1];
    float* U = g_U[z];
    int kbase = (z & 1) * 2048;
    int n0 = blockIdx.x * 64;
    int m0 = blockIdx.y * 128;
    int tid = threadIdx.x;
    int lane = tid & 31, warp = tid >> 5;
    int wm = (warp & 3) * 32;
    int wn = (warp >> 2) * 32;

    float acc[2][4][4];
#pragma unroll
    for (int i = 0; i < 2; ++i)
#pragma unroll
        for (int j = 0; j < 4; ++j)
#pragma unroll
            for (int l = 0; l < 4; ++l) acc[i][j][l] = 0.f;

    auto load_stage = [&](int it, int s) {
        int kb = kbase + it * 32;
#pragma unroll
        for (int i = 0; i < 2; ++i) {
            int ch = tid + i * 256;
            int row = ch >> 2, c8 = (ch & 3) * 8;
            size_t goff = (size_t)(m0 + row) * HIDc + kb + c8;
            uint32_t so = (uint32_t)(s * 128 * 40 + row * 40 + c8);
            CP16(sptr(Ah + so), Xh + goff);
            CP16(sptr(Al + so), Xl + goff);
        }
        {
            int row = tid >> 2, c8 = (tid & 3) * 8;
            size_t goff = (size_t)(n0 + row) * HIDc + kb + c8;
            uint32_t so = (uint32_t)(s * 64 * 40 + row * 40 + c8);
            CP16(sptr(Bh + so), Wh + goff);
            CP16(sptr(Bl + so), Wl + goff);
        }
    };

    const int NIT = 2048 / 32;
    load_stage(0, 0); CPCOMMIT();

    for (int it = 0; it < NIT; ++it) {
        if (it + 1 < NIT) { load_stage(it + 1, (it + 1) & 1); CPCOMMIT(); CPWAIT(1); }
        else              { CPWAIT(0); }
        __syncthreads();
        const __half* Ahs = Ah + (it & 1) * 128 * 40;
        const __half* Als = Al + (it & 1) * 128 * 40;
        const __half* Bhs = Bh + (it & 1) * 64 * 40;
        const __half* Bls = Bl + (it & 1) * 64 * 40;
#pragma unroll
        for (int ks = 0; ks < 2; ++ks) {
            uint32_t ah[2][4], al[2][4];
#pragma unroll
            for (int mf = 0; mf < 2; ++mf) {
                int r = wm + mf * 16 + (lane & 15);
                int c = ks * 16 + 8 * (lane >> 4);
                LDSM4(ah[mf], sptr(Ahs + r * 40 + c));
                LDSM4(al[mf], sptr(Als + r * 40 + c));
            }
            uint32_t bh[2][4], bl[2][4];
#pragma unroll
            for (int p = 0; p < 2; ++p) {
                int r = wn + p * 16 + (lane & 7) + ((lane & 16) >> 1);
                int c = ks * 16 + (lane & 8);
                LDSM4(bh[p], sptr(Bhs + r * 40 + c));
                LDSM4(bl[p], sptr(Bls + r * 40 + c));
            }
#pragma unroll
            for (int mf = 0; mf < 2; ++mf)
#pragma unroll
                for (int nt = 0; nt < 4; ++nt) {
                    uint32_t* bhp = &bh[nt >> 1][(nt & 1) * 2];
                    uint32_t* blp = &bl[nt >> 1][(nt & 1) * 2];
                    MMA16816(acc[mf][nt], ah[mf], bhp[0], bhp[1]);
                    MMA16816(acc[mf][nt], ah[mf], blp[0], blp[1]);
                    MMA16816(acc[mf][nt], al[mf], bhp[0], bhp[1]);
                }
        }
        __syncthreads();
    }
#pragma unroll
    for (int mf = 0; mf < 2; ++mf)
#pragma unroll
        for (int nt = 0; nt < 4; ++nt) {
            int r = m0 + wm + mf * 16 + (lane >> 2);
            int c = n0 + wn + nt * 8 + (lane & 3) * 2;
            *(float2*)&U[(size_t)r * LOc + c]       = make_float2(acc[mf][nt][0], acc[mf][nt][1]);
            *(float2*)&U[(size_t)(r + 8) * LOc + c] = make_float2(acc[mf][nt][2], acc[mf][nt][3]);
        }
}

// ---------------- GEMM2: P(fp16) = (Uh+Ul) * Wb^T, scattered -------------------
__global__ __launch_bounds__(256) void gemm2_tc() {
    extern __shared__ __half sm[];
    __half* Ah = sm;                     // [2][128*40]
    __half* Al = Ah + 2 * 128 * 40;
    __half* Bh = Al + 2 * 128 * 40;
    __half* Bl = Bh + 2 * 128 * 40;

    int z = blockIdx.z;
    const __half* Uh = g_Uh[z];
    const __half* Ul = g_Ul[z];
    const __half* Wh = g_Wbh[z];
    const __half* Wl = g_Wbl[z];
    __half* P = g_Ph[z];
    int n0 = blockIdx.x * 128;
    int m0 = blockIdx.y * 128;
    int tid = threadIdx.x;
    int lane = tid & 31, warp = tid >> 5;
    int wm = (warp & 3) * 32;
    int wn = (warp >> 2) * 64;

    float acc[2][8][4];
#pragma unroll
    for (int i = 0; i < 2; ++i)
#pragma unroll
        for (int j = 0; j < 8; ++j)
#pragma unroll
            for (int l = 0; l < 4; ++l) acc[i][j][l] = 0.f;

    auto load_stage = [&](int it, int s) {
        int kb = it * 32;
#pragma unroll
        for (int i = 0; i < 2; ++i) {
            int ch = tid + i * 256;
            int row = ch >> 2, c8 = (ch & 3) * 8;
            uint32_t so = (uint32_t)(s * 128 * 40 + row * 40 + c8);
            size_t ga = (size_t)(m0 + row) * LOc + kb + c8;
            CP16(sptr(Ah + so), Uh + ga);
            CP16(sptr(Al + so), Ul + ga);
            size_t gb = (size_t)(n0 + row) * LOc + kb + c8;
            CP16(sptr(Bh + so), Wh + gb);
            CP16(sptr(Bl + so), Wl + gb);
        }
    };

    const int NIT = LOc / 32;
    load_stage(0, 0); CPCOMMIT();

    for (int it = 0; it < NIT; ++it) {
        if (it + 1 < NIT) { load_stage(it + 1, (it + 1) & 1); CPCOMMIT(); CPWAIT(1); }
        else              { CPWAIT(0); }
        __syncthreads();
        const __half* Ahs = Ah + (it & 1) * 128 * 40;
        const __half* Als = Al + (it & 1) * 128 * 40;
        const __half* Bhs = Bh + (it & 1) * 128 * 40;
        const __half* Bls = Bl + (it & 1) * 128 * 40;
#pragma unroll
        for (int ks = 0; ks < 2; ++ks) {
            uint32_t ah[2][4], al[2][4];
#pragma unroll
            for (int mf = 0; mf < 2; ++mf) {
                int r = wm + mf * 16 + (lane & 15);
                int c = ks * 16 + 8 * (lane >> 4);
                LDSM4(ah[mf], sptr(Ahs + r * 40 + c));
                LDSM4(al[mf], sptr(Als + r * 40 + c));
            }
            uint32_t bh[4][4], bl[4][4];
#pragma unroll
            for (int p = 0; p < 4; ++p) {
                int r = wn + p * 16 + (lane & 7) + ((lane & 16) >> 1);
                int c = ks * 16 + (lane & 8);
                LDSM4(bh[p], sptr(Bhs + r * 40 + c));
                LDSM4(bl[p], sptr(Bls + r * 40 + c));
            }
#pragma unroll
            for (int mf = 0; mf < 2; ++mf)
#pragma unroll
                for (int nt = 0; nt < 8; ++nt) {
                    uint32_t* bhp = &bh[nt >> 1][(nt & 1) * 2];
                    uint32_t* blp = &bl[nt >> 1][(nt & 1) * 2];
                    MMA16816(acc[mf][nt], ah[mf], bhp[0], bhp[1]);
                    MMA16816(acc[mf][nt], ah[mf], blp[0], blp[1]);
                    MMA16816(acc[mf][nt], al[mf], bhp[0], bhp[1]);
                }
        }
        __syncthreads();
    }
#pragma unroll
    for (int mf = 0; mf < 2; ++mf)
#pragma unroll
        for (int nt = 0; nt < 8; ++nt) {
            int r = m0 + wm + mf * 16 + (lane >> 2);
            int c = n0 + wn + nt * 8 + (lane & 3) * 2;
            int h = c >> 7, d = c & 127;
            int bb = r >> 10, s = r & 1023;
            size_t base = (((size_t)(bb * Hc + h)) * Sc + s) * Dc + d;
            *(__half2*)&P[base]          = __floats2half2_rn(acc[mf][nt][0], acc[mf][nt][1]);
            *(__half2*)&P[base + 8 * Dc] = __floats2half2_rn(acc[mf][nt][2], acc[mf][nt][3]);
        }
}

// ---------------- fused attention + block pooling ------------------------------
__global__ __launch_bounds__(256) void attn_tc(const float* __restrict__ alpha_p) {
    extern __shared__ __half sm[];
    __half* Qs = sm;                 // [128][136]
    __half* Ks = Qs + 128 * 136;     // [2][64][136]

    int qt = 7 - blockIdx.x;         // heavy first
    int bh = blockIdx.y;
    int b = bh >> 5;
    int q0 = qt * 128;
    int tid = threadIdx.x;
    int lane = tid & 31, warp = tid >> 5;

    const __half* Qp = g_Ph[0] + (size_t)bh * Sc * Dc;
    const __half* Kp = g_Ph[1] + (size_t)bh * Sc * Dc;

#pragma unroll
    for (int i = 0; i < 8; ++i) {
        int ch = tid + i * 256;
        int row = ch >> 4, c8 = (ch & 15) * 8;
        CP16(sptr(Qs + row * 136 + c8), Qp + (size_t)(q0 + row) * Dc + c8);
    }
    auto load_k = [&](int kt, int s) {
        int k0 = kt * 64;
#pragma unroll
        for (int i = 0; i < 4; ++i) {
            int ch = tid + i * 256;
            int row = ch >> 4, c8 = (ch & 15) * 8;
            CP16(sptr(Ks + s * 64 * 136 + row * 136 + c8), Kp + (size_t)(k0 + row) * Dc + c8);
        }
    };
    load_k(0, 0); CPCOMMIT();

    float ab[2][4];
#pragma unroll
    for (int i = 0; i < 2; ++i)
#pragma unroll
        for (int n = 0; n < 4; ++n) ab[i][n] = 0.f;

    int r0g = q0 + warp * 16 + (lane >> 2);
    int NT = 2 * qt + 2;

    for (int kt = 0; kt < NT; ++kt) {
        if (kt + 1 < NT) { load_k(kt + 1, (kt + 1) & 1); CPCOMMIT(); CPWAIT(1); }
        else             { CPWAIT(0); }
        __syncthreads();

        const __half* Kss = Ks + (kt & 1) * 64 * 136;
        float acc[8][4];
#pragma unroll
        for (int j = 0; j < 8; ++j)
#pragma unroll
            for (int l = 0; l < 4; ++l) acc[j][l] = 0.f;

#pragma unroll
        for (int ks = 0; ks < 8; ++ks) {
            uint32_t a[4];
            {
                int r = warp * 16 + (lane & 15);
                int c = ks * 16 + 8 * (lane >> 4);
                LDSM4(a, sptr(Qs + r * 136 + c));
            }
            uint32_t bf[4][4];
#pragma unroll
            for (int p = 0; p < 4; ++p) {
                int r = p * 16 + (lane & 7) + ((lane & 16) >> 1);
                int c = ks * 16 + (lane & 8);
                LDSM4(bf[p], sptr(Kss + r * 136 + c));
            }
#pragma unroll
            for (int nt = 0; nt < 8; ++nt) {
                uint32_t* bp = &bf[nt >> 1][(nt & 1) * 2];
                MMA16816(acc[nt], a, bp[0], bp[1]);
            }
        }
        __syncthreads();

        int k0 = kt * 64;
        int u = __ldg(&g_tblk[b * 16 + (k0 >> 6)]);
        bool needmask = (kt >= 2 * qt);
        float s0 = 0.f, s1 = 0.f;
#pragma unroll
        for (int nt = 0; nt < 8; ++nt) {
            int c0 = k0 + nt * 8 + (lane & 3) * 2;
            float e00 = fexp2s(acc[nt][0]);
            float e01 = fexp2s(acc[nt][1]);
            float e10 = fexp2s(acc[nt][2]);
            float e11 = fexp2s(acc[nt][3]);
            if (needmask) {
                if (c0 > r0g)         e00 = 0.f;
                if (c0 + 1 > r0g)     e01 = 0.f;
                if (c0 > r0g + 8)     e10 = 0.f;
                if (c0 + 1 > r0g + 8) e11 = 0.f;
            }
            if (u >= 0) {
                s0 += e00 + e01;
                s1 += e10 + e11;
            } else {
                int b0 = __ldg(&g_blk[b * Sc + c0]);
                int b1 = __ldg(&g_blk[b * Sc + c0 + 1]);
#pragma unroll
                for (int n = 0; n < 4; ++n) {
                    ab[0][n] += (b0 == n ? e00 : 0.f) + (b1 == n ? e01 : 0.f);
                    ab[1][n] += (b0 == n ? e10 : 0.f) + (b1 == n ? e11 : 0.f);
                }
            }
        }
        if (u >= 0) {
#pragma unroll
            for (int n = 0; n < 4; ++n) {
                ab[0][n] += (n == u) ? s0 : 0.f;
                ab[1][n] += (n == u) ? s1 : 0.f;
            }
        }
    }

#pragma unroll
    for (int off = 1; off <= 2; off <<= 1)
#pragma unroll
        for (int i = 0; i < 2; ++i)
#pragma unroll
            for (int n = 0; n < 4; ++n)
                ab[i][n] += __shfl_xor_sync(0xffffffffu, ab[i][n], off, 32);

    if ((lane & 3) == 0) {
        float alpha = *alpha_p;
#pragma unroll
        for (int i = 0; i < 2; ++i) {
            int r = r0g + i * 8;
            float Z = ab[i][0] + ab[i][1] + ab[i][2] + ab[i][3];
            float inv = alpha / Z;
            const float* cnt = &g_cnt[(b * Sc + r) * NBc];
            float* dst = &g_w[((size_t)bh * Sc + r) * NBc];
#pragma unroll
            for (int n = 0; n < NBc; ++n)
                dst[n] = ab[i][n] * inv / fmaxf(cnt[n], 1.f);
        }
    }
}

// ---------------- expand --------------------------------------------------------
__global__ void expand_kernel(float* __restrict__ out) {
    int row = blockIdx.x;
    int q = row & (Sc - 1);
    int bh = row >> 10;
    int b = bh >> 5;
    float4 w4 = __ldg((const float4*)&g_w[(size_t)row * NBc]);
    int k = threadIdx.x * 4;
    int4 bl = *(const int4*)&g_blk[b * Sc + k];
    float4 o;
    o.x = (k + 0 <= q) ? (bl.x == 0 ? w4.x : bl.x == 1 ? w4.y : bl.x == 2 ? w4.z : w4.w) : 0.f;
    o.y = (k + 1 <= q) ? (bl.y == 0 ? w4.x : bl.y == 1 ? w4.y : bl.y == 2 ? w4.z : w4.w) : 0.f;
    o.z = (k + 2 <= q) ? (bl.z == 0 ? w4.x : bl.z == 1 ? w4.y : bl.z == 2 ? w4.z : w4.w) : 0.f;
    o.w = (k + 3 <= q) ? (bl.w == 0 ? w4.x : bl.w == 1 ? w4.y : bl.w == 2 ? w4.z : w4.w) : 0.f;
    *(float4*)(out + (size_t)row * Sc + k) = o;
}

// ---------------- launch --------------------------------------------------------
extern "C" void kernel_launch(void* const* d_in, const int* in_sizes, int n_in,
                              void* d_out, int out_size) {
    const float* query = (const float*)d_in[0];
    const float* key   = (const float*)d_in[1];
    const float* Wqa   = (const float*)d_in[2];
    const float* Wqb   = (const float*)d_in[3];
    const float* Wka   = (const float*)d_in[4];
    const float* Wkb   = (const float*)d_in[5];
    const float* alpha = (const float*)d_in[6];
    const float* bmask = (const float*)d_in[7];
    float* out = (float*)d_out;

    const int SM_G1 = (2 * 128 * 40 * 2 + 2 * 64 * 40 * 2) * 2;   // 61440 B
    const int SM_G2 = (2 * 128 * 40 * 4) * 2;                     // 81920 B
    const int SM_AT = (128 * 136 + 2 * 64 * 136) * 2;             // 69632 B
    cudaFuncSetAttribute(gemm1_tc, cudaFuncAttributeMaxDynamicSharedMemorySize, SM_G1);
    cudaFuncSetAttribute(gemm2_tc, cudaFuncAttributeMaxDynamicSharedMemorySize, SM_G2);
    cudaFuncSetAttribute(attn_tc,  cudaFuncAttributeMaxDynamicSharedMemorySize, SM_AT);

    prep_kernel<<<Bc, 256>>>(bmask);
    xsplit_kernel<<<dim3(8192, 2), 256>>>(query, key);
    wsplit_kernel<<<2048, 256>>>(Wqa, 0);
    wsplit_kernel<<<2048, 256>>>(Wka, 1);
    wsplit_kernel<<<2048, 256>>>(Wqb, 2);
    wsplit_kernel<<<2048, 256>>>(Wkb, 3);

    gemm1_tc<<<dim3(LOc / 64, Mc / 128, 4), 256, SM_G1>>>();
    uconv_kernel<<<dim3(1024, 2), 256>>>();
    gemm2_tc<<<dim3(HIDc / 128, Mc / 128, 2), 256, SM_G2>>>();
    attn_tc<<<dim3(8, Bc * Hc), 256, SM_AT>>>(alpha);
    expand_kernel<<<Bc * Hc * Sc, 256>>>(out);
}

// round 6
// speedup vs baseline: 4.8493x; 1.6007x over previous
#include <cuda_runtime.h>
#include <cuda_fp16.h>
#include <math.h>
#include <stdint.h>

#define Bc   2
#define Hc   32
#define Sc   1024
#define Dc   128
#define NBc  4
#define HIDc 4096
#define LOc  512
#define Mc   (Bc*Sc)

// ---------------- device scratch ---------------------------------------------
__device__ __half g_Xh[2][(size_t)Mc * HIDc];
__device__ __half g_Wah[2][(size_t)LOc * HIDc];
__device__ __half g_Wbh[2][(size_t)HIDc * LOc];
__device__ __half g_Uh[2][(size_t)Mc * LOc];
__device__ __half g_Ph[2][(size_t)Bc * Hc * Sc * Dc];
__device__ float  g_w[(size_t)Bc * Hc * Sc * NBc];
__device__ int    g_blk[Bc * Sc];
__device__ int    g_tblk[Bc * 16];
__device__ float  g_cnt[Bc * Sc * NBc];

// ---------------- PTX helpers -------------------------------------------------
__device__ __forceinline__ uint32_t sptr(const void* p) {
    return (uint32_t)__cvta_generic_to_shared(p);
}
#define LDSM4(r, addr) asm volatile( \
    "ldmatrix.sync.aligned.m8n8.x4.shared.b16 {%0,%1,%2,%3}, [%4];" \
    : "=r"((r)[0]), "=r"((r)[1]), "=r"((r)[2]), "=r"((r)[3]) : "r"(addr))
#define MMA16816(c, a, b0, b1) asm volatile( \
    "mma.sync.aligned.m16n8k16.row.col.f32.f16.f16.f32 " \
    "{%0,%1,%2,%3},{%4,%5,%6,%7},{%8,%9},{%0,%1,%2,%3};" \
    : "+f"((c)[0]), "+f"((c)[1]), "+f"((c)[2]), "+f"((c)[3]) \
    : "r"((a)[0]), "r"((a)[1]), "r"((a)[2]), "r"((a)[3]), "r"(b0), "r"(b1))
#define CP16(dst, src) asm volatile( \
    "cp.async.cg.shared.global [%0], [%1], 16;" :: "r"(dst), "l"(src))
#define CPCOMMIT() asm volatile("cp.async.commit_group;")
#define CPWAIT(N)  asm volatile("cp.async.wait_group %0;" :: "n"(N))

// base-2 exp with 1/sqrt(D)*log2(e) prefolded; FMA-pipe only
__device__ __forceinline__ float fexp2s(float x) {
    const float CS = 0.08838834764831843f * 1.4426950408889634f;
    float t = fmaxf(x * CS, -110.f);
    float r = t + 12582912.f;
    int   i = __float_as_int(r) - 0x4B400000;
    float f = t - (r - 12582912.f);
    float p = 1.3333558e-3f;
    p = fmaf(p, f, 9.6181291e-3f);
    p = fmaf(p, f, 5.5504109e-2f);
    p = fmaf(p, f, 2.4022651e-1f);
    p = fmaf(p, f, 6.9314718e-1f);
    p = fmaf(p, f, 1.0f);
    return __int_as_float(__float_as_int(p) + (i << 23));
}

__device__ __forceinline__ void cvt4(float4 v, __half* dst) {
    *(__half2*)(dst)     = __floats2half2_rn(v.x, v.y);
    *(__half2*)(dst + 2) = __floats2half2_rn(v.z, v.w);
}

// ---------------- prep ---------------------------------------------------------
__global__ void prep_kernel(const float* __restrict__ bmask) {
    int b = blockIdx.x;
    __shared__ int sblk[Sc];
    for (int k = threadIdx.x; k < Sc; k += blockDim.x) {
        int n = 0;
        for (int j = NBc - 1; j >= 0; --j)
            if (bmask[(b * NBc + j) * Sc + k] > 0.5f) n = j;
        sblk[k] = n;
        g_blk[b * Sc + k] = n;
    }
    __syncthreads();
    for (int q = threadIdx.x; q < Sc; q += blockDim.x) {
        int c0 = 0, c1 = 0, c2 = 0, c3 = 0;
        for (int k = 0; k <= q; ++k) {
            int n = sblk[k];
            c0 += (n == 0); c1 += (n == 1); c2 += (n == 2); c3 += (n == 3);
        }
        float* dst = &g_cnt[(b * Sc + q) * NBc];
        dst[0] = (float)c0; dst[1] = (float)c1; dst[2] = (float)c2; dst[3] = (float)c3;
    }
    if (threadIdx.x < 16) {
        int t = threadIdx.x;
        int u = sblk[t * 64];
        bool uni = true;
        for (int j = 1; j < 64; ++j) uni &= (sblk[t * 64 + j] == u);
        g_tblk[b * 16 + t] = uni ? u : -1;
    }
}

// ---------------- conversions (device-side global resolution — ATS bug!) -------
__global__ void xsplit_kernel(const float* __restrict__ q, const float* __restrict__ k) {
    int z = blockIdx.y;
    const float* X = z ? k : q;
    __half* Hh = g_Xh[z];
    size_t i4 = (size_t)blockIdx.x * blockDim.x + threadIdx.x;   // < 2048*1024
    int m = (int)(i4 >> 10);
    int c = (int)(i4 & 1023) * 4;
    int h = c >> 7, d = c & 127, b = m >> 10, s = m & 1023;
    float4 v = *(const float4*)(X + (((size_t)(b * Hc + h)) * Sc + s) * Dc + d);
    cvt4(v, Hh + i4 * 4);
}

__global__ void wsplit_kernel(const float* __restrict__ src, int sel) {
    __half* hi;
    switch (sel) {
        case 0:  hi = g_Wah[0]; break;
        case 1:  hi = g_Wah[1]; break;
        case 2:  hi = g_Wbh[0]; break;
        default: hi = g_Wbh[1]; break;
    }
    size_t i4 = (size_t)blockIdx.x * blockDim.x + threadIdx.x;   // < 524288
    float4 v = ((const float4*)src)[i4];
    cvt4(v, hi + i4 * 4);
}

// ---------------- GEMM1: U(fp16) = X * Wa^T  (plain fp16, cp.async dbuf) -------
__global__ __launch_bounds__(256) void gemm1_tc() {
    extern __shared__ __half sm[];
    __half* Ah = sm;                     // [2][128*40]
    __half* Bh = Ah + 2 * 128 * 40;      // [2][64*40]

    int z = blockIdx.z;                  // 0=q, 1=k
    const __half* Xh = g_Xh[z];
    const __half* Wh = g_Wah[z];
    __half* U = g_Uh[z];
    int n0 = blockIdx.x * 64;
    int m0 = blockIdx.y * 128;
    int tid = threadIdx.x;
    int lane = tid & 31, warp = tid >> 5;
    int wm = (warp & 3) * 32;
    int wn = (warp >> 2) * 32;

    float acc[2][4][4];
#pragma unroll
    for (int i = 0; i < 2; ++i)
#pragma unroll
        for (int j = 0; j < 4; ++j)
#pragma unroll
            for (int l = 0; l < 4; ++l) acc[i][j][l] = 0.f;

    auto load_stage = [&](int it, int s) {
        int kb = it * 32;
#pragma unroll
        for (int i = 0; i < 2; ++i) {
            int ch = tid + i * 256;
            int row = ch >> 2, c8 = (ch & 3) * 8;
            CP16(sptr(Ah + s * 128 * 40 + row * 40 + c8),
                 Xh + (size_t)(m0 + row) * HIDc + kb + c8);
        }
        {
            int row = tid >> 2, c8 = (tid & 3) * 8;
            CP16(sptr(Bh + s * 64 * 40 + row * 40 + c8),
                 Wh + (size_t)(n0 + row) * HIDc + kb + c8);
        }
    };

    const int NIT = HIDc / 32;
    load_stage(0, 0); CPCOMMIT();

    for (int it = 0; it < NIT; ++it) {
        if (it + 1 < NIT) { load_stage(it + 1, (it + 1) & 1); CPCOMMIT(); CPWAIT(1); }
        else              { CPWAIT(0); }
        __syncthreads();
        const __half* Ahs = Ah + (it & 1) * 128 * 40;
        const __half* Bhs = Bh + (it & 1) * 64 * 40;
#pragma unroll
        for (int ks = 0; ks < 2; ++ks) {
            uint32_t ah[2][4];
#pragma unroll
            for (int mf = 0; mf < 2; ++mf) {
                int r = wm + mf * 16 + (lane & 15);
                int c = ks * 16 + 8 * (lane >> 4);
                LDSM4(ah[mf], sptr(Ahs + r * 40 + c));
            }
            uint32_t bh[2][4];
#pragma unroll
            for (int p = 0; p < 2; ++p) {
                int r = wn + p * 16 + (lane & 7) + ((lane & 16) >> 1);
                int c = ks * 16 + (lane & 8);
                LDSM4(bh[p], sptr(Bhs + r * 40 + c));
            }
#pragma unroll
            for (int mf = 0; mf < 2; ++mf)
#pragma unroll
                for (int nt = 0; nt < 4; ++nt) {
                    uint32_t* bp = &bh[nt >> 1][(nt & 1) * 2];
                    MMA16816(acc[mf][nt], ah[mf], bp[0], bp[1]);
                }
        }
        __syncthreads();
    }
#pragma unroll
    for (int mf = 0; mf < 2; ++mf)
#pragma unroll
        for (int nt = 0; nt < 4; ++nt) {
            int r = m0 + wm + mf * 16 + (lane >> 2);
            int c = n0 + wn + nt * 8 + (lane & 3) * 2;
            *(__half2*)&U[(size_t)r * LOc + c] =
                __floats2half2_rn(acc[mf][nt][0], acc[mf][nt][1]);
            *(__half2*)&U[(size_t)(r + 8) * LOc + c] =
                __floats2half2_rn(acc[mf][nt][2], acc[mf][nt][3]);
        }
}

// ---------------- GEMM2: P(fp16) = U * Wb^T, scattered --------------------------
__global__ __launch_bounds__(256) void gemm2_tc() {
    extern __shared__ __half sm[];
    __half* Ah = sm;                     // [2][128*40]
    __half* Bh = Ah + 2 * 128 * 40;      // [2][128*40]

    int z = blockIdx.z;
    const __half* Uh = g_Uh[z];
    const __half* Wh = g_Wbh[z];
    __half* P = g_Ph[z];
    int n0 = blockIdx.x * 128;
    int m0 = blockIdx.y * 128;
    int tid = threadIdx.x;
    int lane = tid & 31, warp = tid >> 5;
    int wm = (warp & 3) * 32;
    int wn = (warp >> 2) * 64;

    float acc[2][8][4];
#pragma unroll
    for (int i = 0; i < 2; ++i)
#pragma unroll
        for (int j = 0; j < 8; ++j)
#pragma unroll
            for (int l = 0; l < 4; ++l) acc[i][j][l] = 0.f;

    auto load_stage = [&](int it, int s) {
        int kb = it * 32;
#pragma unroll
        for (int i = 0; i < 2; ++i) {
            int ch = tid + i * 256;
            int row = ch >> 2, c8 = (ch & 3) * 8;
            CP16(sptr(Ah + s * 128 * 40 + row * 40 + c8),
                 Uh + (size_t)(m0 + row) * LOc + kb + c8);
            CP16(sptr(Bh + s * 128 * 40 + row * 40 + c8),
                 Wh + (size_t)(n0 + row) * LOc + kb + c8);
        }
    };

    const int NIT = LOc / 32;
    load_stage(0, 0); CPCOMMIT();

    for (int it = 0; it < NIT; ++it) {
        if (it + 1 < NIT) { load_stage(it + 1, (it + 1) & 1); CPCOMMIT(); CPWAIT(1); }
        else              { CPWAIT(0); }
        __syncthreads();
        const __half* Ahs = Ah + (it & 1) * 128 * 40;
        const __half* Bhs = Bh + (it & 1) * 128 * 40;
#pragma unroll
        for (int ks = 0; ks < 2; ++ks) {
            uint32_t ah[2][4];
#pragma unroll
            for (int mf = 0; mf < 2; ++mf) {
                int r = wm + mf * 16 + (lane & 15);
                int c = ks * 16 + 8 * (lane >> 4);
                LDSM4(ah[mf], sptr(Ahs + r * 40 + c));
            }
            uint32_t bh[4][4];
#pragma unroll
            for (int p = 0; p < 4; ++p) {
                int r = wn + p * 16 + (lane & 7) + ((lane & 16) >> 1);
                int c = ks * 16 + (lane & 8);
                LDSM4(bh[p], sptr(Bhs + r * 40 + c));
            }
#pragma unroll
            for (int mf = 0; mf < 2; ++mf)
#pragma unroll
                for (int nt = 0; nt < 8; ++nt) {
                    uint32_t* bp = &bh[nt >> 1][(nt & 1) * 2];
                    MMA16816(acc[mf][nt], ah[mf], bp[0], bp[1]);
                }
        }
        __syncthreads();
    }
#pragma unroll
    for (int mf = 0; mf < 2; ++mf)
#pragma unroll
        for (int nt = 0; nt < 8; ++nt) {
            int r = m0 + wm + mf * 16 + (lane >> 2);
            int c = n0 + wn + nt * 8 + (lane & 3) * 2;
            int h = c >> 7, d = c & 127;
            int bb = r >> 10, s = r & 1023;
            size_t base = (((size_t)(bb * Hc + h)) * Sc + s) * Dc + d;
            *(__half2*)&P[base]          = __floats2half2_rn(acc[mf][nt][0], acc[mf][nt][1]);
            *(__half2*)&P[base + 8 * Dc] = __floats2half2_rn(acc[mf][nt][2], acc[mf][nt][3]);
        }
}

// ---------------- fused attention + block pooling ------------------------------
__global__ __launch_bounds__(256) void attn_tc(const float* __restrict__ alpha_p) {
    extern __shared__ __half sm[];
    __half* Qs = sm;                 // [128][136]
    __half* Ks = Qs + 128 * 136;     // [2][64][136]

    int qt = 7 - blockIdx.x;
    int bh = blockIdx.y;
    int b = bh >> 5;
    int q0 = qt * 128;
    int tid = threadIdx.x;
    int lane = tid & 31, warp = tid >> 5;

    const __half* Qp = g_Ph[0] + (size_t)bh * Sc * Dc;
    const __half* Kp = g_Ph[1] + (size_t)bh * Sc * Dc;

#pragma unroll
    for (int i = 0; i < 8; ++i) {
        int ch = tid + i * 256;
        int row = ch >> 4, c8 = (ch & 15) * 8;
        CP16(sptr(Qs + row * 136 + c8), Qp + (size_t)(q0 + row) * Dc + c8);
    }
    auto load_k = [&](int kt, int s) {
        int k0 = kt * 64;
#pragma unroll
        for (int i = 0; i < 4; ++i) {
            int ch = tid + i * 256;
            int row = ch >> 4, c8 = (ch & 15) * 8;
            CP16(sptr(Ks + s * 64 * 136 + row * 136 + c8), Kp + (size_t)(k0 + row) * Dc + c8);
        }
    };
    load_k(0, 0); CPCOMMIT();

    float ab[2][4];
#pragma unroll
    for (int i = 0; i < 2; ++i)
#pragma unroll
        for (int n = 0; n < 4; ++n) ab[i][n] = 0.f;

    int r0g = q0 + warp * 16 + (lane >> 2);
    int NT = 2 * qt + 2;

    for (int kt = 0; kt < NT; ++kt) {
        if (kt + 1 < NT) { load_k(kt + 1, (kt + 1) & 1); CPCOMMIT(); CPWAIT(1); }
        else             { CPWAIT(0); }
        __syncthreads();

        const __half* Kss = Ks + (kt & 1) * 64 * 136;
        float acc[8][4];
#pragma unroll
        for (int j = 0; j < 8; ++j)
#pragma unroll
            for (int l = 0; l < 4; ++l) acc[j][l] = 0.f;

#pragma unroll
        for (int ks = 0; ks < 8; ++ks) {
            uint32_t a[4];
            {
                int r = warp * 16 + (lane & 15);
                int c = ks * 16 + 8 * (lane >> 4);
                LDSM4(a, sptr(Qs + r * 136 + c));
            }
            uint32_t bf[4][4];
#pragma unroll
            for (int p = 0; p < 4; ++p) {
                int r = p * 16 + (lane & 7) + ((lane & 16) >> 1);
                int c = ks * 16 + (lane & 8);
                LDSM4(bf[p], sptr(Kss + r * 136 + c));
            }
#pragma unroll
            for (int nt = 0; nt < 8; ++nt) {
                uint32_t* bp = &bf[nt >> 1][(nt & 1) * 2];
                MMA16816(acc[nt], a, bp[0], bp[1]);
            }
        }
        __syncthreads();

        int k0 = kt * 64;
        int u = __ldg(&g_tblk[b * 16 + (k0 >> 6)]);
        bool needmask = (kt >= 2 * qt);
        float s0 = 0.f, s1 = 0.f;
#pragma unroll
        for (int nt = 0; nt < 8; ++nt) {
            int c0 = k0 + nt * 8 + (lane & 3) * 2;
            float e00 = fexp2s(acc[nt][0]);
            float e01 = fexp2s(acc[nt][1]);
            float e10 = fexp2s(acc[nt][2]);
            float e11 = fexp2s(acc[nt][3]);
            if (needmask) {
                if (c0 > r0g)         e00 = 0.f;
                if (c0 + 1 > r0g)     e01 = 0.f;
                if (c0 > r0g + 8)     e10 = 0.f;
                if (c0 + 1 > r0g + 8) e11 = 0.f;
            }
            if (u >= 0) {
                s0 += e00 + e01;
                s1 += e10 + e11;
            } else {
                int b0 = __ldg(&g_blk[b * Sc + c0]);
                int b1 = __ldg(&g_blk[b * Sc + c0 + 1]);
#pragma unroll
                for (int n = 0; n < 4; ++n) {
                    ab[0][n] += (b0 == n ? e00 : 0.f) + (b1 == n ? e01 : 0.f);
                    ab[1][n] += (b0 == n ? e10 : 0.f) + (b1 == n ? e11 : 0.f);
                }
            }
        }
        if (u >= 0) {
#pragma unroll
            for (int n = 0; n < 4; ++n) {
                ab[0][n] += (n == u) ? s0 : 0.f;
                ab[1][n] += (n == u) ? s1 : 0.f;
            }
        }
    }

#pragma unroll
    for (int off = 1; off <= 2; off <<= 1)
#pragma unroll
        for (int i = 0; i < 2; ++i)
#pragma unroll
            for (int n = 0; n < 4; ++n)
                ab[i][n] += __shfl_xor_sync(0xffffffffu, ab[i][n], off, 32);

    if ((lane & 3) == 0) {
        float alpha = *alpha_p;
#pragma unroll
        for (int i = 0; i < 2; ++i) {
            int r = r0g + i * 8;
            float Z = ab[i][0] + ab[i][1] + ab[i][2] + ab[i][3];
            float inv = alpha / Z;
            const float* cnt = &g_cnt[(b * Sc + r) * NBc];
            float* dst = &g_w[((size_t)bh * Sc + r) * NBc];
#pragma unroll
            for (int n = 0; n < NBc; ++n)
                dst[n] = ab[i][n] * inv / fmaxf(cnt[n], 1.f);
        }
    }
}

// ---------------- expand --------------------------------------------------------
__global__ void expand_kernel(float* __restrict__ out) {
    int row = blockIdx.x;
    int q = row & (Sc - 1);
    int bh = row >> 10;
    int b = bh >> 5;
    float4 w4 = __ldg((const float4*)&g_w[(size_t)row * NBc]);
    int k = threadIdx.x * 4;
    int4 bl = *(const int4*)&g_blk[b * Sc + k];
    float4 o;
    o.x = (k + 0 <= q) ? (bl.x == 0 ? w4.x : bl.x == 1 ? w4.y : bl.x == 2 ? w4.z : w4.w) : 0.f;
    o.y = (k + 1 <= q) ? (bl.y == 0 ? w4.x : bl.y == 1 ? w4.y : bl.y == 2 ? w4.z : w4.w) : 0.f;
    o.z = (k + 2 <= q) ? (bl.z == 0 ? w4.x : bl.z == 1 ? w4.y : bl.z == 2 ? w4.z : w4.w) : 0.f;
    o.w = (k + 3 <= q) ? (bl.w == 0 ? w4.x : bl.w == 1 ? w4.y : bl.w == 2 ? w4.z : w4.w) : 0.f;
    *(float4*)(out + (size_t)row * Sc + k) = o;
}

// ---------------- launch --------------------------------------------------------
extern "C" void kernel_launch(void* const* d_in, const int* in_sizes, int n_in,
                              void* d_out, int out_size) {
    const float* query = (const float*)d_in[0];
    const float* key   = (const float*)d_in[1];
    const float* Wqa   = (const float*)d_in[2];
    const float* Wqb   = (const float*)d_in[3];
    const float* Wka   = (const float*)d_in[4];
    const float* Wkb   = (const float*)d_in[5];
    const float* alpha = (const float*)d_in[6];
    const float* bmask = (const float*)d_in[7];
    float* out = (float*)d_out;

    const int SM_G1 = (2 * 128 * 40 + 2 * 64 * 40) * 2;   // 30720 B
    const int SM_G2 = (2 * 128 * 40 * 2) * 2;             // 40960 B
    const int SM_AT = (128 * 136 + 2 * 64 * 136) * 2;     // 69632 B
    cudaFuncSetAttribute(gemm1_tc, cudaFuncAttributeMaxDynamicSharedMemorySize, SM_G1);
    cudaFuncSetAttribute(gemm2_tc, cudaFuncAttributeMaxDynamicSharedMemorySize, SM_G2);
    cudaFuncSetAttribute(attn_tc,  cudaFuncAttributeMaxDynamicSharedMemorySize, SM_AT);

    // Launch order chosen so gemm1_tc is launch index 5 (ncu -s 5 -c 1 target).
    prep_kernel<<<Bc, 256>>>(bmask);                       // 0
    xsplit_kernel<<<dim3(8192, 2), 256>>>(query, key);     // 1
    wsplit_kernel<<<2048, 256>>>(Wqa, 0);                  // 2
    wsplit_kernel<<<2048, 256>>>(Wka, 1);                  // 3
    wsplit_kernel<<<2048, 256>>>(Wqb, 2);                  // 4
    gemm1_tc<<<dim3(LOc / 64, Mc / 128, 2), 256, SM_G1>>>();   // 5  <-- profiled
    wsplit_kernel<<<2048, 256>>>(Wkb, 3);                  // 6
    gemm2_tc<<<dim3(HIDc / 128, Mc / 128, 2), 256, SM_G2>>>(); // 7
    attn_tc<<<dim3(8, Bc * Hc), 256, SM_AT>>>(alpha);      // 8
    expand_kernel<<<Bc * Hc * Sc, 256>>>(out);             // 9
}

// round 8
// speedup vs baseline: 4.8980x; 1.0100x over previous
#include <cuda_runtime.h>
#include <cuda_fp16.h>
#include <math.h>
#include <stdint.h>

#define Bc   2
#define Hc   32
#define Sc   1024
#define Dc   128
#define NBc  4
#define HIDc 4096
#define LOc  512
#define Mc   (Bc*Sc)

// ---------------- device scratch ---------------------------------------------
__device__ __half g_Xh[2][(size_t)Mc * HIDc];
__device__ __half g_Wah[2][(size_t)LOc * HIDc];
__device__ __half g_Wbh[2][(size_t)HIDc * LOc];
__device__ __half g_Uh[2][(size_t)Mc * LOc];
__device__ __half g_Ph[2][(size_t)Bc * Hc * Sc * Dc];
__device__ float  g_w[(size_t)Bc * Hc * Sc * NBc];
__device__ int    g_blk[Bc * Sc];
__device__ int    g_tblk[Bc * 16];
__device__ float  g_cnt[Bc * Sc * NBc];

// ---------------- PTX helpers -------------------------------------------------
__device__ __forceinline__ uint32_t sptr(const void* p) {
    return (uint32_t)__cvta_generic_to_shared(p);
}
#define LDSM4(r, addr) asm volatile( \
    "ldmatrix.sync.aligned.m8n8.x4.shared.b16 {%0,%1,%2,%3}, [%4];" \
    : "=r"((r)[0]), "=r"((r)[1]), "=r"((r)[2]), "=r"((r)[3]) : "r"(addr))
#define MMA16816(c, a, b0, b1) asm volatile( \
    "mma.sync.aligned.m16n8k16.row.col.f32.f16.f16.f32 " \
    "{%0,%1,%2,%3},{%4,%5,%6,%7},{%8,%9},{%0,%1,%2,%3};" \
    : "+f"((c)[0]), "+f"((c)[1]), "+f"((c)[2]), "+f"((c)[3]) \
    : "r"((a)[0]), "r"((a)[1]), "r"((a)[2]), "r"((a)[3]), "r"(b0), "r"(b1))
#define CP16(dst, src) asm volatile( \
    "cp.async.cg.shared.global [%0], [%1], 16;" :: "r"(dst), "l"(src))
#define CPCOMMIT() asm volatile("cp.async.commit_group;")
#define CPWAIT(N)  asm volatile("cp.async.wait_group %0;" :: "n"(N))

// base-2 exp with 1/sqrt(D)*log2(e) prefolded; FMA-pipe only
__device__ __forceinline__ float fexp2s(float x) {
    const float CS = 0.08838834764831843f * 1.4426950408889634f;
    float t = fmaxf(x * CS, -110.f);
    float r = t + 12582912.f;
    int   i = __float_as_int(r) - 0x4B400000;
    float f = t - (r - 12582912.f);
    float p = 1.3333558e-3f;
    p = fmaf(p, f, 9.6181291e-3f);
    p = fmaf(p, f, 5.5504109e-2f);
    p = fmaf(p, f, 2.4022651e-1f);
    p = fmaf(p, f, 6.9314718e-1f);
    p = fmaf(p, f, 1.0f);
    return __int_as_float(__float_as_int(p) + (i << 23));
}

__device__ __forceinline__ void cvt4(float4 v, __half* dst) {
    *(__half2*)(dst)     = __floats2half2_rn(v.x, v.y);
    *(__half2*)(dst + 2) = __floats2half2_rn(v.z, v.w);
}

// ---------------- prep ---------------------------------------------------------
__global__ void prep_kernel(const float* __restrict__ bmask) {
    int b = blockIdx.x;
    __shared__ int sblk[Sc];
    for (int k = threadIdx.x; k < Sc; k += blockDim.x) {
        int n = 0;
        for (int j = NBc - 1; j >= 0; --j)
            if (bmask[(b * NBc + j) * Sc + k] > 0.5f) n = j;
        sblk[k] = n;
        g_blk[b * Sc + k] = n;
    }
    __syncthreads();
    for (int q = threadIdx.x; q < Sc; q += blockDim.x) {
        int c0 = 0, c1 = 0, c2 = 0, c3 = 0;
        for (int k = 0; k <= q; ++k) {
            int n = sblk[k];
            c0 += (n == 0); c1 += (n == 1); c2 += (n == 2); c3 += (n == 3);
        }
        float* dst = &g_cnt[(b * Sc + q) * NBc];
        dst[0] = (float)c0; dst[1] = (float)c1; dst[2] = (float)c2; dst[3] = (float)c3;
    }
    if (threadIdx.x < 16) {
        int t = threadIdx.x;
        int u = sblk[t * 64];
        bool uni = true;
        for (int j = 1; j < 64; ++j) uni &= (sblk[t * 64 + j] == u);
        g_tblk[b * 16 + t] = uni ? u : -1;
    }
}

// ---------------- conversions (device-side global resolution — ATS bug!) -------
__global__ void xsplit_kernel(const float* __restrict__ q, const float* __restrict__ k) {
    int z = blockIdx.y;
    const float* X = z ? k : q;
    __half* Hh = g_Xh[z];
    size_t i4 = (size_t)blockIdx.x * blockDim.x + threadIdx.x;   // < 2048*1024
    int m = (int)(i4 >> 10);
    int c = (int)(i4 & 1023) * 4;
    int h = c >> 7, d = c & 127, b = m >> 10, s = m & 1023;
    float4 v = *(const float4*)(X + (((size_t)(b * Hc + h)) * Sc + s) * Dc + d);
    cvt4(v, Hh + i4 * 4);
}

// all 4 weights in one launch; destinations resolved device-side.
__global__ void wsplit_kernel(const float* __restrict__ wqa, const float* __restrict__ wka,
                              const float* __restrict__ wqb, const float* __restrict__ wkb) {
    int sel = blockIdx.y;
    const float* src;
    __half* hi;
    switch (sel) {
        case 0:  src = wqa; hi = g_Wah[0]; break;
        case 1:  src = wka; hi = g_Wah[1]; break;
        case 2:  src = wqb; hi = g_Wbh[0]; break;
        default: src = wkb; hi = g_Wbh[1]; break;
    }
    size_t i4 = (size_t)blockIdx.x * blockDim.x + threadIdx.x;   // < 524288
    float4 v = ((const float4*)src)[i4];
    cvt4(v, hi + i4 * 4);
}

// ---------------- GEMM1: U(fp16) = X * Wa^T  (fp16, 3-stage cp.async) ----------
__global__ __launch_bounds__(256) void gemm1_tc() {
    extern __shared__ __half sm[];
    __half* Ah = sm;                     // [3][128*40]
    __half* Bh = Ah + 3 * 128 * 40;      // [3][64*40]

    int z = blockIdx.z;
    const __half* Xh = g_Xh[z];
    const __half* Wh = g_Wah[z];
    __half* U = g_Uh[z];
    int n0 = blockIdx.x * 64;
    int m0 = blockIdx.y * 128;
    int tid = threadIdx.x;
    int lane = tid & 31, warp = tid >> 5;
    int wm = (warp & 3) * 32;
    int wn = (warp >> 2) * 32;

    float acc[2][4][4];
#pragma unroll
    for (int i = 0; i < 2; ++i)
#pragma unroll
        for (int j = 0; j < 4; ++j)
#pragma unroll
            for (int l = 0; l < 4; ++l) acc[i][j][l] = 0.f;

    auto load_stage = [&](int it, int s) {
        int kb = it * 32;
#pragma unroll
        for (int i = 0; i < 2; ++i) {
            int ch = tid + i * 256;
            int row = ch >> 2, c8 = (ch & 3) * 8;
            CP16(sptr(Ah + s * 128 * 40 + row * 40 + c8),
                 Xh + (size_t)(m0 + row) * HIDc + kb + c8);
        }
        {
            int row = tid >> 2, c8 = (tid & 3) * 8;
            CP16(sptr(Bh + s * 64 * 40 + row * 40 + c8),
                 Wh + (size_t)(n0 + row) * HIDc + kb + c8);
        }
    };

    const int NIT = HIDc / 32;
    load_stage(0, 0); CPCOMMIT();
    load_stage(1, 1); CPCOMMIT();

    int s = 0;
    for (int it = 0; it < NIT; ++it) {
        CPWAIT(1);              // stage `it` resident (invariant: G0..G_it complete)
        __syncthreads();        // compute(it-1) reads done -> safe to overwrite its slot
        if (it + 2 < NIT) load_stage(it + 2, (s + 2) % 3);   // FIXED slot rotation
        CPCOMMIT();             // always commit (possibly empty) to keep group math valid
        const __half* Ahs = Ah + s * 128 * 40;
        const __half* Bhs = Bh + s * 64 * 40;
#pragma unroll
        for (int ks = 0; ks < 2; ++ks) {
            uint32_t ah[2][4];
#pragma unroll
            for (int mf = 0; mf < 2; ++mf) {
                int r = wm + mf * 16 + (lane & 15);
                int c = ks * 16 + 8 * (lane >> 4);
                LDSM4(ah[mf], sptr(Ahs + r * 40 + c));
            }
            uint32_t bh[2][4];
#pragma unroll
            for (int p = 0; p < 2; ++p) {
                int r = wn + p * 16 + (lane & 7) + ((lane & 16) >> 1);
                int c = ks * 16 + (lane & 8);
                LDSM4(bh[p], sptr(Bhs + r * 40 + c));
            }
#pragma unroll
            for (int mf = 0; mf < 2; ++mf)
#pragma unroll
                for (int nt = 0; nt < 4; ++nt) {
                    uint32_t* bp = &bh[nt >> 1][(nt & 1) * 2];
                    MMA16816(acc[mf][nt], ah[mf], bp[0], bp[1]);
                }
        }
        s = (s + 1 == 3) ? 0 : s + 1;
    }
#pragma unroll
    for (int mf = 0; mf < 2; ++mf)
#pragma unroll
        for (int nt = 0; nt < 4; ++nt) {
            int r = m0 + wm + mf * 16 + (lane >> 2);
            int c = n0 + wn + nt * 8 + (lane & 3) * 2;
            *(__half2*)&U[(size_t)r * LOc + c] =
                __floats2half2_rn(acc[mf][nt][0], acc[mf][nt][1]);
            *(__half2*)&U[(size_t)(r + 8) * LOc + c] =
                __floats2half2_rn(acc[mf][nt][2], acc[mf][nt][3]);
        }
}

// ---------------- GEMM2: P(fp16) = U * Wb^T, scattered, 3-stage ----------------
__global__ __launch_bounds__(256) void gemm2_tc() {
    extern __shared__ __half sm[];
    __half* Ah = sm;                     // [3][128*40]
    __half* Bh = Ah + 3 * 128 * 40;      // [3][128*40]

    int z = blockIdx.z;
    const __half* Uh = g_Uh[z];
    const __half* Wh = g_Wbh[z];
    __half* P = g_Ph[z];
    int n0 = blockIdx.x * 128;
    int m0 = blockIdx.y * 128;
    int tid = threadIdx.x;
    int lane = tid & 31, warp = tid >> 5;
    int wm = (warp & 3) * 32;
    int wn = (warp >> 2) * 64;

    float acc[2][8][4];
#pragma unroll
    for (int i = 0; i < 2; ++i)
#pragma unroll
        for (int j = 0; j < 8; ++j)
#pragma unroll
            for (int l = 0; l < 4; ++l) acc[i][j][l] = 0.f;

    auto load_stage = [&](int it, int s) {
        int kb = it * 32;
#pragma unroll
        for (int i = 0; i < 2; ++i) {
            int ch = tid + i * 256;
            int row = ch >> 2, c8 = (ch & 3) * 8;
            CP16(sptr(Ah + s * 128 * 40 + row * 40 + c8),
                 Uh + (size_t)(m0 + row) * LOc + kb + c8);
            CP16(sptr(Bh + s * 128 * 40 + row * 40 + c8),
                 Wh + (size_t)(n0 + row) * LOc + kb + c8);
        }
    };

    const int NIT = LOc / 32;
    load_stage(0, 0); CPCOMMIT();
    load_stage(1, 1); CPCOMMIT();

    int s = 0;
    for (int it = 0; it < NIT; ++it) {
        CPWAIT(1);
        __syncthreads();
        if (it + 2 < NIT) load_stage(it + 2, (s + 2) % 3);
        CPCOMMIT();
        const __half* Ahs = Ah + s * 128 * 40;
        const __half* Bhs = Bh + s * 128 * 40;
#pragma unroll
        for (int ks = 0; ks < 2; ++ks) {
            uint32_t ah[2][4];
#pragma unroll
            for (int mf = 0; mf < 2; ++mf) {
                int r = wm + mf * 16 + (lane & 15);
                int c = ks * 16 + 8 * (lane >> 4);
                LDSM4(ah[mf], sptr(Ahs + r * 40 + c));
            }
            uint32_t bh[4][4];
#pragma unroll
            for (int p = 0; p < 4; ++p) {
                int r = wn + p * 16 + (lane & 7) + ((lane & 16) >> 1);
                int c = ks * 16 + (lane & 8);
                LDSM4(bh[p], sptr(Bhs + r * 40 + c));
            }
#pragma unroll
            for (int mf = 0; mf < 2; ++mf)
#pragma unroll
                for (int nt = 0; nt < 8; ++nt) {
                    uint32_t* bp = &bh[nt >> 1][(nt & 1) * 2];
                    MMA16816(acc[mf][nt], ah[mf], bp[0], bp[1]);
                }
        }
        s = (s + 1 == 3) ? 0 : s + 1;
    }
#pragma unroll
    for (int mf = 0; mf < 2; ++mf)
#pragma unroll
        for (int nt = 0; nt < 8; ++nt) {
            int r = m0 + wm + mf * 16 + (lane >> 2);
            int c = n0 + wn + nt * 8 + (lane & 3) * 2;
            int h = c >> 7, d = c & 127;
            int bb = r >> 10, s2 = r & 1023;
            size_t base = (((size_t)(bb * Hc + h)) * Sc + s2) * Dc + d;
            *(__half2*)&P[base]          = __floats2half2_rn(acc[mf][nt][0], acc[mf][nt][1]);
            *(__half2*)&P[base + 8 * Dc] = __floats2half2_rn(acc[mf][nt][2], acc[mf][nt][3]);
        }
}

// ---------------- fused attention + block pooling (3-stage K pipeline) ---------
__global__ __launch_bounds__(256) void attn_tc(const float* __restrict__ alpha_p) {
    extern __shared__ __half sm[];
    __half* Qs = sm;                 // [128][136]
    __half* Ks = Qs + 128 * 136;     // [3][64][136]

    int qt = 7 - blockIdx.x;
    int bh = blockIdx.y;
    int b = bh >> 5;
    int q0 = qt * 128;
    int tid = threadIdx.x;
    int lane = tid & 31, warp = tid >> 5;

    const __half* Qp = g_Ph[0] + (size_t)bh * Sc * Dc;
    const __half* Kp = g_Ph[1] + (size_t)bh * Sc * Dc;

#pragma unroll
    for (int i = 0; i < 8; ++i) {
        int ch = tid + i * 256;
        int row = ch >> 4, c8 = (ch & 15) * 8;
        CP16(sptr(Qs + row * 136 + c8), Qp + (size_t)(q0 + row) * Dc + c8);
    }
    auto load_k = [&](int kt, int s) {
        int k0 = kt * 64;
#pragma unroll
        for (int i = 0; i < 4; ++i) {
            int ch = tid + i * 256;
            int row = ch >> 4, c8 = (ch & 15) * 8;
            CP16(sptr(Ks + s * 64 * 136 + row * 136 + c8), Kp + (size_t)(k0 + row) * Dc + c8);
        }
    };

    int NT = 2 * qt + 2;
    load_k(0, 0); CPCOMMIT();
    load_k(1, 1); CPCOMMIT();

    float ab[2][4];
#pragma unroll
    for (int i = 0; i < 2; ++i)
#pragma unroll
        for (int n = 0; n < 4; ++n) ab[i][n] = 0.f;

    int r0g = q0 + warp * 16 + (lane >> 2);
    int s = 0;

    for (int kt = 0; kt < NT; ++kt) {
        CPWAIT(1);
        __syncthreads();
        if (kt + 2 < NT) load_k(kt + 2, (s + 2) % 3);
        CPCOMMIT();

        const __half* Kss = Ks + s * 64 * 136;
        float acc[8][4];
#pragma unroll
        for (int j = 0; j < 8; ++j)
#pragma unroll
            for (int l = 0; l < 4; ++l) acc[j][l] = 0.f;

#pragma unroll
        for (int ks = 0; ks < 8; ++ks) {
            uint32_t a[4];
            {
                int r = warp * 16 + (lane & 15);
                int c = ks * 16 + 8 * (lane >> 4);
                LDSM4(a, sptr(Qs + r * 136 + c));
            }
            uint32_t bf[4][4];
#pragma unroll
            for (int p = 0; p < 4; ++p) {
                int r = p * 16 + (lane & 7) + ((lane & 16) >> 1);
                int c = ks * 16 + (lane & 8);
                LDSM4(bf[p], sptr(Kss + r * 136 + c));
            }
#pragma unroll
            for (int nt = 0; nt < 8; ++nt) {
                uint32_t* bp = &bf[nt >> 1][(nt & 1) * 2];
                MMA16816(acc[nt], a, bp[0], bp[1]);
            }
        }

        int k0 = kt * 64;
        int u = __ldg(&g_tblk[b * 16 + (k0 >> 6)]);
        bool needmask = (kt >= 2 * qt);
        float s0 = 0.f, s1 = 0.f;
#pragma unroll
        for (int nt = 0; nt < 8; ++nt) {
            int c0 = k0 + nt * 8 + (lane & 3) * 2;
            float e00 = fexp2s(acc[nt][0]);
            float e01 = fexp2s(acc[nt][1]);
            float e10 = fexp2s(acc[nt][2]);
            float e11 = fexp2s(acc[nt][3]);
            if (needmask) {
                if (c0 > r0g)         e00 = 0.f;
                if (c0 + 1 > r0g)     e01 = 0.f;
                if (c0 > r0g + 8)     e10 = 0.f;
                if (c0 + 1 > r0g + 8) e11 = 0.f;
            }
            if (u >= 0) {
                s0 += e00 + e01;
                s1 += e10 + e11;
            } else {
                int b0 = __ldg(&g_blk[b * Sc + c0]);
                int b1 = __ldg(&g_blk[b * Sc + c0 + 1]);
#pragma unroll
                for (int n = 0; n < 4; ++n) {
                    ab[0][n] += (b0 == n ? e00 : 0.f) + (b1 == n ? e01 : 0.f);
                    ab[1][n] += (b0 == n ? e10 : 0.f) + (b1 == n ? e11 : 0.f);
                }
            }
        }
        if (u >= 0) {
#pragma unroll
            for (int n = 0; n < 4; ++n) {
                ab[0][n] += (n == u) ? s0 : 0.f;
                ab[1][n] += (n == u) ? s1 : 0.f;
            }
        }
        s = (s + 1 == 3) ? 0 : s + 1;
    }

#pragma unroll
    for (int off = 1; off <= 2; off <<= 1)
#pragma unroll
        for (int i = 0; i < 2; ++i)
#pragma unroll
            for (int n = 0; n < 4; ++n)
                ab[i][n] += __shfl_xor_sync(0xffffffffu, ab[i][n], off, 32);

    if ((lane & 3) == 0) {
        float alpha = *alpha_p;
#pragma unroll
        for (int i = 0; i < 2; ++i) {
            int r = r0g + i * 8;
            float Z = ab[i][0] + ab[i][1] + ab[i][2] + ab[i][3];
            float inv = alpha / Z;
            const float* cnt = &g_cnt[(b * Sc + r) * NBc];
            float* dst = &g_w[((size_t)bh * Sc + r) * NBc];
#pragma unroll
            for (int n = 0; n < NBc; ++n)
                dst[n] = ab[i][n] * inv / fmaxf(cnt[n], 1.f);
        }
    }
}

// ---------------- expand --------------------------------------------------------
__global__ void expand_kernel(float* __restrict__ out) {
    int row = blockIdx.x;
    int q = row & (Sc - 1);
    int bh = row >> 10;
    int b = bh >> 5;
    float4 w4 = __ldg((const float4*)&g_w[(size_t)row * NBc]);
    int k = threadIdx.x * 4;
    int4 bl = *(const int4*)&g_blk[b * Sc + k];
    float4 o;
    o.x = (k + 0 <= q) ? (bl.x == 0 ? w4.x : bl.x == 1 ? w4.y : bl.x == 2 ? w4.z : w4.w) : 0.f;
    o.y = (k + 1 <= q) ? (bl.y == 0 ? w4.x : bl.y == 1 ? w4.y : bl.y == 2 ? w4.z : w4.w) : 0.f;
    o.z = (k + 2 <= q) ? (bl.z == 0 ? w4.x : bl.z == 1 ? w4.y : bl.z == 2 ? w4.z : w4.w) : 0.f;
    o.w = (k + 3 <= q) ? (bl.w == 0 ? w4.x : bl.w == 1 ? w4.y : bl.w == 2 ? w4.z : w4.w) : 0.f;
    *(float4*)(out + (size_t)row * Sc + k) = o;
}

// ---------------- launch --------------------------------------------------------
extern "C" void kernel_launch(void* const* d_in, const int* in_sizes, int n_in,
                              void* d_out, int out_size) {
    const float* query = (const float*)d_in[0];
    const float* key   = (const float*)d_in[1];
    const float* Wqa   = (const float*)d_in[2];
    const float* Wqb   = (const float*)d_in[3];
    const float* Wka   = (const float*)d_in[4];
    const float* Wkb   = (const float*)d_in[5];
    const float* alpha = (const float*)d_in[6];
    const float* bmask = (const float*)d_in[7];
    float* out = (float*)d_out;

    const int SM_G1 = (3 * 128 * 40 + 3 * 64 * 40) * 2;   // 46080 B
    const int SM_G2 = (3 * 128 * 40 * 2) * 2;             // 61440 B
    const int SM_AT = (128 * 136 + 3 * 64 * 136) * 2;     // 87040 B
    cudaFuncSetAttribute(gemm1_tc, cudaFuncAttributeMaxDynamicSharedMemorySize, SM_G1);
    cudaFuncSetAttribute(gemm2_tc, cudaFuncAttributeMaxDynamicSharedMemorySize, SM_G2);
    cudaFuncSetAttribute(attn_tc,  cudaFuncAttributeMaxDynamicSharedMemorySize, SM_AT);

    prep_kernel<<<Bc, 256>>>(bmask);
    xsplit_kernel<<<dim3(8192, 2), 256>>>(query, key);
    wsplit_kernel<<<dim3(2048, 4), 256>>>(Wqa, Wka, Wqb, Wkb);
    gemm1_tc<<<dim3(LOc / 64, Mc / 128, 2), 256, SM_G1>>>();
    gemm2_tc<<<dim3(HIDc / 128, Mc / 128, 2), 256, SM_G2>>>();
    attn_tc<<<dim3(8, Bc * Hc), 256, SM_AT>>>(alpha);
    expand_kernel<<<Bc * Hc * Sc, 256>>>(out);
}

// round 9
// speedup vs baseline: 4.9191x; 1.0043x over previous
#include <cuda_runtime.h>
#include <cuda_fp16.h>
#include <math.h>
#include <stdint.h>

#define Bc   2
#define Hc   32
#define Sc   1024
#define Dc   128
#define NBc  4
#define HIDc 4096
#define LOc  512
#define Mc   (Bc*Sc)

// ---------------- device scratch ---------------------------------------------
__device__ __half g_Xh[2][(size_t)Mc * HIDc];
__device__ __half g_Wah[2][(size_t)LOc * HIDc];
__device__ __half g_Wbh[2][(size_t)HIDc * LOc];
__device__ float  g_U32[4][(size_t)Mc * LOc];      // split-K partials (q0,q1,k0,k1)
__device__ __half g_Uh[2][(size_t)Mc * LOc];
__device__ __half g_Ph[2][(size_t)Bc * Hc * Sc * Dc];
__device__ float  g_w[(size_t)Bc * Hc * Sc * NBc];
__device__ int    g_blk[Bc * Sc];
__device__ int    g_tblk[Bc * 16];
__device__ float  g_cnt[Bc * Sc * NBc];

// ---------------- PTX helpers -------------------------------------------------
__device__ __forceinline__ uint32_t sptr(const void* p) {
    return (uint32_t)__cvta_generic_to_shared(p);
}
#define LDSM4(r, addr) asm volatile( \
    "ldmatrix.sync.aligned.m8n8.x4.shared.b16 {%0,%1,%2,%3}, [%4];" \
    : "=r"((r)[0]), "=r"((r)[1]), "=r"((r)[2]), "=r"((r)[3]) : "r"(addr))
#define MMA16816(c, a, b0, b1) asm volatile( \
    "mma.sync.aligned.m16n8k16.row.col.f32.f16.f16.f32 " \
    "{%0,%1,%2,%3},{%4,%5,%6,%7},{%8,%9},{%0,%1,%2,%3};" \
    : "+f"((c)[0]), "+f"((c)[1]), "+f"((c)[2]), "+f"((c)[3]) \
    : "r"((a)[0]), "r"((a)[1]), "r"((a)[2]), "r"((a)[3]), "r"(b0), "r"(b1))
#define CP16(dst, src) asm volatile( \
    "cp.async.cg.shared.global [%0], [%1], 16;" :: "r"(dst), "l"(src))
#define CPCOMMIT() asm volatile("cp.async.commit_group;")
#define CPWAIT(N)  asm volatile("cp.async.wait_group %0;" :: "n"(N))

// base-2 exp with 1/sqrt(D)*log2(e) prefolded; FMA-pipe only
__device__ __forceinline__ float fexp2s(float x) {
    const float CS = 0.08838834764831843f * 1.4426950408889634f;
    float t = fmaxf(x * CS, -110.f);
    float r = t + 12582912.f;
    int   i = __float_as_int(r) - 0x4B400000;
    float f = t - (r - 12582912.f);
    float p = 1.3333558e-3f;
    p = fmaf(p, f, 9.6181291e-3f);
    p = fmaf(p, f, 5.5504109e-2f);
    p = fmaf(p, f, 2.4022651e-1f);
    p = fmaf(p, f, 6.9314718e-1f);
    p = fmaf(p, f, 1.0f);
    return __int_as_float(__float_as_int(p) + (i << 23));
}

__device__ __forceinline__ void cvt4(float4 v, __half* dst) {
    *(__half2*)(dst)     = __floats2half2_rn(v.x, v.y);
    *(__half2*)(dst + 2) = __floats2half2_rn(v.z, v.w);
}

// ---------------- prep ---------------------------------------------------------
__global__ void prep_kernel(const float* __restrict__ bmask) {
    int b = blockIdx.x;
    __shared__ int sblk[Sc];
    for (int k = threadIdx.x; k < Sc; k += blockDim.x) {
        int n = 0;
        for (int j = NBc - 1; j >= 0; --j)
            if (bmask[(b * NBc + j) * Sc + k] > 0.5f) n = j;
        sblk[k] = n;
        g_blk[b * Sc + k] = n;
    }
    __syncthreads();
    for (int q = threadIdx.x; q < Sc; q += blockDim.x) {
        int c0 = 0, c1 = 0, c2 = 0, c3 = 0;
        for (int k = 0; k <= q; ++k) {
            int n = sblk[k];
            c0 += (n == 0); c1 += (n == 1); c2 += (n == 2); c3 += (n == 3);
        }
        float* dst = &g_cnt[(b * Sc + q) * NBc];
        dst[0] = (float)c0; dst[1] = (float)c1; dst[2] = (float)c2; dst[3] = (float)c3;
    }
    if (threadIdx.x < 16) {
        int t = threadIdx.x;
        int u = sblk[t * 64];
        bool uni = true;
        for (int j = 1; j < 64; ++j) uni &= (sblk[t * 64 + j] == u);
        g_tblk[b * 16 + t] = uni ? u : -1;
    }
}

// ---------------- conversions (device-side global resolution — ATS bug!) -------
__global__ void xsplit_kernel(const float* __restrict__ q, const float* __restrict__ k) {
    int z = blockIdx.y;
    const float* X = z ? k : q;
    __half* Hh = g_Xh[z];
    size_t i4 = (size_t)blockIdx.x * blockDim.x + threadIdx.x;   // < 2048*1024
    int m = (int)(i4 >> 10);
    int c = (int)(i4 & 1023) * 4;
    int h = c >> 7, d = c & 127, b = m >> 10, s = m & 1023;
    float4 v = *(const float4*)(X + (((size_t)(b * Hc + h)) * Sc + s) * Dc + d);
    cvt4(v, Hh + i4 * 4);
}

__global__ void wsplit_kernel(const float* __restrict__ wqa, const float* __restrict__ wka,
                              const float* __restrict__ wqb, const float* __restrict__ wkb) {
    int sel = blockIdx.y;
    const float* src;
    __half* hi;
    switch (sel) {
        case 0:  src = wqa; hi = g_Wah[0]; break;
        case 1:  src = wka; hi = g_Wah[1]; break;
        case 2:  src = wqb; hi = g_Wbh[0]; break;
        default: src = wkb; hi = g_Wbh[1]; break;
    }
    size_t i4 = (size_t)blockIdx.x * blockDim.x + threadIdx.x;   // < 524288
    float4 v = ((const float4*)src)[i4];
    cvt4(v, hi + i4 * 4);
}

// combine split-K partials -> fp16 U
__global__ void ucomb_kernel() {
    int z = blockIdx.y;
    size_t i4 = (size_t)blockIdx.x * blockDim.x + threadIdx.x;   // < 262144
    float4 a = ((const float4*)g_U32[2 * z])[i4];
    float4 b = ((const float4*)g_U32[2 * z + 1])[i4];
    a.x += b.x; a.y += b.y; a.z += b.z; a.w += b.w;
    cvt4(a, g_Uh[z] + i4 * 4);
}

// ---------------- GEMM1: U32 partial = X * Wa^T (fp16 MMA, splitK=2, 3-stage) --
__global__ __launch_bounds__(256) void gemm1_tc() {
    extern __shared__ __half sm[];
    __half* Ah = sm;                     // [3][128*40]
    __half* Bh = Ah + 3 * 128 * 40;      // [3][64*40]

    int z = blockIdx.z;                  // bit1: q/k, bit0: K-split
    const __half* Xh = g_Xh[z >> 1];
    const __half* Wh = g_Wah[z >> 1];
    float* U = g_U32[z];
    int kbase = (z & 1) * (HIDc / 2);
    int n0 = blockIdx.x * 64;
    int m0 = blockIdx.y * 128;
    int tid = threadIdx.x;
    int lane = tid & 31, warp = tid >> 5;
    int wm = (warp & 3) * 32;
    int wn = (warp >> 2) * 32;

    float acc[2][4][4];
#pragma unroll
    for (int i = 0; i < 2; ++i)
#pragma unroll
        for (int j = 0; j < 4; ++j)
#pragma unroll
            for (int l = 0; l < 4; ++l) acc[i][j][l] = 0.f;

    auto load_stage = [&](int it, int s) {
        int kb = kbase + it * 32;
#pragma unroll
        for (int i = 0; i < 2; ++i) {
            int ch = tid + i * 256;
            int row = ch >> 2, c8 = (ch & 3) * 8;
            CP16(sptr(Ah + s * 128 * 40 + row * 40 + c8),
                 Xh + (size_t)(m0 + row) * HIDc + kb + c8);
        }
        {
            int row = tid >> 2, c8 = (tid & 3) * 8;
            CP16(sptr(Bh + s * 64 * 40 + row * 40 + c8),
                 Wh + (size_t)(n0 + row) * HIDc + kb + c8);
        }
    };

    const int NIT = (HIDc / 2) / 32;     // 64
    load_stage(0, 0); CPCOMMIT();
    load_stage(1, 1); CPCOMMIT();

    int s = 0;
    for (int it = 0; it < NIT; ++it) {
        CPWAIT(1);
        __syncthreads();
        if (it + 2 < NIT) load_stage(it + 2, (s + 2) % 3);
        CPCOMMIT();
        const __half* Ahs = Ah + s * 128 * 40;
        const __half* Bhs = Bh + s * 64 * 40;
#pragma unroll
        for (int ks = 0; ks < 2; ++ks) {
            uint32_t ah[2][4];
#pragma unroll
            for (int mf = 0; mf < 2; ++mf) {
                int r = wm + mf * 16 + (lane & 15);
                int c = ks * 16 + 8 * (lane >> 4);
                LDSM4(ah[mf], sptr(Ahs + r * 40 + c));
            }
            uint32_t bh[2][4];
#pragma unroll
            for (int p = 0; p < 2; ++p) {
                int r = wn + p * 16 + (lane & 7) + ((lane & 16) >> 1);
                int c = ks * 16 + (lane & 8);
                LDSM4(bh[p], sptr(Bhs + r * 40 + c));
            }
#pragma unroll
            for (int mf = 0; mf < 2; ++mf)
#pragma unroll
                for (int nt = 0; nt < 4; ++nt) {
                    uint32_t* bp = &bh[nt >> 1][(nt & 1) * 2];
                    MMA16816(acc[mf][nt], ah[mf], bp[0], bp[1]);
                }
        }
        s = (s + 1 == 3) ? 0 : s + 1;
    }
#pragma unroll
    for (int mf = 0; mf < 2; ++mf)
#pragma unroll
        for (int nt = 0; nt < 4; ++nt) {
            int r = m0 + wm + mf * 16 + (lane >> 2);
            int c = n0 + wn + nt * 8 + (lane & 3) * 2;
            *(float2*)&U[(size_t)r * LOc + c]       = make_float2(acc[mf][nt][0], acc[mf][nt][1]);
            *(float2*)&U[(size_t)(r + 8) * LOc + c] = make_float2(acc[mf][nt][2], acc[mf][nt][3]);
        }
}

// ---------------- GEMM2: P(fp16) = U * Wb^T, scattered, 3-stage ----------------
__global__ __launch_bounds__(256) void gemm2_tc() {
    extern __shared__ __half sm[];
    __half* Ah = sm;                     // [3][128*40]
    __half* Bh = Ah + 3 * 128 * 40;      // [3][128*40]

    int z = blockIdx.z;
    const __half* Uh = g_Uh[z];
    const __half* Wh = g_Wbh[z];
    __half* P = g_Ph[z];
    int n0 = blockIdx.x * 128;
    int m0 = blockIdx.y * 128;
    int tid = threadIdx.x;
    int lane = tid & 31, warp = tid >> 5;
    int wm = (warp & 3) * 32;
    int wn = (warp >> 2) * 64;

    float acc[2][8][4];
#pragma unroll
    for (int i = 0; i < 2; ++i)
#pragma unroll
        for (int j = 0; j < 8; ++j)
#pragma unroll
            for (int l = 0; l < 4; ++l) acc[i][j][l] = 0.f;

    auto load_stage = [&](int it, int s) {
        int kb = it * 32;
#pragma unroll
        for (int i = 0; i < 2; ++i) {
            int ch = tid + i * 256;
            int row = ch >> 2, c8 = (ch & 3) * 8;
            CP16(sptr(Ah + s * 128 * 40 + row * 40 + c8),
                 Uh + (size_t)(m0 + row) * LOc + kb + c8);
            CP16(sptr(Bh + s * 128 * 40 + row * 40 + c8),
                 Wh + (size_t)(n0 + row) * LOc + kb + c8);
        }
    };

    const int NIT = LOc / 32;
    load_stage(0, 0); CPCOMMIT();
    load_stage(1, 1); CPCOMMIT();

    int s = 0;
    for (int it = 0; it < NIT; ++it) {
        CPWAIT(1);
        __syncthreads();
        if (it + 2 < NIT) load_stage(it + 2, (s + 2) % 3);
        CPCOMMIT();
        const __half* Ahs = Ah + s * 128 * 40;
        const __half* Bhs = Bh + s * 128 * 40;
#pragma unroll
        for (int ks = 0; ks < 2; ++ks) {
            uint32_t ah[2][4];
#pragma unroll
            for (int mf = 0; mf < 2; ++mf) {
                int r = wm + mf * 16 + (lane & 15);
                int c = ks * 16 + 8 * (lane >> 4);
                LDSM4(ah[mf], sptr(Ahs + r * 40 + c));
            }
            uint32_t bh[4][4];
#pragma unroll
            for (int p = 0; p < 4; ++p) {
                int r = wn + p * 16 + (lane & 7) + ((lane & 16) >> 1);
                int c = ks * 16 + (lane & 8);
                LDSM4(bh[p], sptr(Bhs + r * 40 + c));
            }
#pragma unroll
            for (int mf = 0; mf < 2; ++mf)
#pragma unroll
                for (int nt = 0; nt < 8; ++nt) {
                    uint32_t* bp = &bh[nt >> 1][(nt & 1) * 2];
                    MMA16816(acc[mf][nt], ah[mf], bp[0], bp[1]);
                }
        }
        s = (s + 1 == 3) ? 0 : s + 1;
    }
#pragma unroll
    for (int mf = 0; mf < 2; ++mf)
#pragma unroll
        for (int nt = 0; nt < 8; ++nt) {
            int r = m0 + wm + mf * 16 + (lane >> 2);
            int c = n0 + wn + nt * 8 + (lane & 3) * 2;
            int h = c >> 7, d = c & 127;
            int bb = r >> 10, s2 = r & 1023;
            size_t base = (((size_t)(bb * Hc + h)) * Sc + s2) * Dc + d;
            *(__half2*)&P[base]          = __floats2half2_rn(acc[mf][nt][0], acc[mf][nt][1]);
            *(__half2*)&P[base + 8 * Dc] = __floats2half2_rn(acc[mf][nt][2], acc[mf][nt][3]);
        }
}

// ---------------- fused attention + block pooling (3-stage K pipeline) ---------
__global__ __launch_bounds__(256) void attn_tc(const float* __restrict__ alpha_p) {
    extern __shared__ __half sm[];
    __half* Qs = sm;                 // [128][136]
    __half* Ks = Qs + 128 * 136;     // [3][64][136]

    int qt = 7 - blockIdx.x;
    int bh = blockIdx.y;
    int b = bh >> 5;
    int q0 = qt * 128;
    int tid = threadIdx.x;
    int lane = tid & 31, warp = tid >> 5;

    const __half* Qp = g_Ph[0] + (size_t)bh * Sc * Dc;
    const __half* Kp = g_Ph[1] + (size_t)bh * Sc * Dc;

#pragma unroll
    for (int i = 0; i < 8; ++i) {
        int ch = tid + i * 256;
        int row = ch >> 4, c8 = (ch & 15) * 8;
        CP16(sptr(Qs + row * 136 + c8), Qp + (size_t)(q0 + row) * Dc + c8);
    }
    auto load_k = [&](int kt, int s) {
        int k0 = kt * 64;
#pragma unroll
        for (int i = 0; i < 4; ++i) {
            int ch = tid + i * 256;
            int row = ch >> 4, c8 = (ch & 15) * 8;
            CP16(sptr(Ks + s * 64 * 136 + row * 136 + c8), Kp + (size_t)(k0 + row) * Dc + c8);
        }
    };

    int NT = 2 * qt + 2;
    load_k(0, 0); CPCOMMIT();
    load_k(1, 1); CPCOMMIT();

    float ab[2][4];
#pragma unroll
    for (int i = 0; i < 2; ++i)
#pragma unroll
        for (int n = 0; n < 4; ++n) ab[i][n] = 0.f;

    int r0g = q0 + warp * 16 + (lane >> 2);
    int s = 0;

    for (int kt = 0; kt < NT; ++kt) {
        CPWAIT(1);
        __syncthreads();
        if (kt + 2 < NT) load_k(kt + 2, (s + 2) % 3);
        CPCOMMIT();

        const __half* Kss = Ks + s * 64 * 136;
        float acc[8][4];
#pragma unroll
        for (int j = 0; j < 8; ++j)
#pragma unroll
            for (int l = 0; l < 4; ++l) acc[j][l] = 0.f;

#pragma unroll
        for (int ks = 0; ks < 8; ++ks) {
            uint32_t a[4];
            {
                int r = warp * 16 + (lane & 15);
                int c = ks * 16 + 8 * (lane >> 4);
                LDSM4(a, sptr(Qs + r * 136 + c));
            }
            uint32_t bf[4][4];
#pragma unroll
            for (int p = 0; p < 4; ++p) {
                int r = p * 16 + (lane & 7) + ((lane & 16) >> 1);
                int c = ks * 16 + (lane & 8);
                LDSM4(bf[p], sptr(Kss + r * 136 + c));
            }
#pragma unroll
            for (int nt = 0; nt < 8; ++nt) {
                uint32_t* bp = &bf[nt >> 1][(nt & 1) * 2];
                MMA16816(acc[nt], a, bp[0], bp[1]);
            }
        }

        int k0 = kt * 64;
        int u = __ldg(&g_tblk[b * 16 + (k0 >> 6)]);
        bool needmask = (kt >= 2 * qt);
        float s0 = 0.f, s1 = 0.f;
#pragma unroll
        for (int nt = 0; nt < 8; ++nt) {
            int c0 = k0 + nt * 8 + (lane & 3) * 2;
            float e00 = fexp2s(acc[nt][0]);
            float e01 = fexp2s(acc[nt][1]);
            float e10 = fexp2s(acc[nt][2]);
            float e11 = fexp2s(acc[nt][3]);
            if (needmask) {
                if (c0 > r0g)         e00 = 0.f;
                if (c0 + 1 > r0g)     e01 = 0.f;
                if (c0 > r0g + 8)     e10 = 0.f;
                if (c0 + 1 > r0g + 8) e11 = 0.f;
            }
            if (u >= 0) {
                s0 += e00 + e01;
                s1 += e10 + e11;
            } else {
                int b0 = __ldg(&g_blk[b * Sc + c0]);
                int b1 = __ldg(&g_blk[b * Sc + c0 + 1]);
#pragma unroll
                for (int n = 0; n < 4; ++n) {
                    ab[0][n] += (b0 == n ? e00 : 0.f) + (b1 == n ? e01 : 0.f);
                    ab[1][n] += (b0 == n ? e10 : 0.f) + (b1 == n ? e11 : 0.f);
                }
            }
        }
        if (u >= 0) {
#pragma unroll
            for (int n = 0; n < 4; ++n) {
                ab[0][n] += (n == u) ? s0 : 0.f;
                ab[1][n] += (n == u) ? s1 : 0.f;
            }
        }
        s = (s + 1 == 3) ? 0 : s + 1;
    }

#pragma unroll
    for (int off = 1; off <= 2; off <<= 1)
#pragma unroll
        for (int i = 0; i < 2; ++i)
#pragma unroll
            for (int n = 0; n < 4; ++n)
                ab[i][n] += __shfl_xor_sync(0xffffffffu, ab[i][n], off, 32);

    if ((lane & 3) == 0) {
        float alpha = *alpha_p;
#pragma unroll
        for (int i = 0; i < 2; ++i) {
            int r = r0g + i * 8;
            float Z = ab[i][0] + ab[i][1] + ab[i][2] + ab[i][3];
            float inv = alpha / Z;
            const float* cnt = &g_cnt[(b * Sc + r) * NBc];
            float* dst = &g_w[((size_t)bh * Sc + r) * NBc];
#pragma unroll
            for (int n = 0; n < NBc; ++n)
                dst[n] = ab[i][n] * inv / fmaxf(cnt[n], 1.f);
        }
    }
}

// ---------------- expand --------------------------------------------------------
__global__ void expand_kernel(float* __restrict__ out) {
    int row = blockIdx.x;
    int q = row & (Sc - 1);
    int bh = row >> 10;
    int b = bh >> 5;
    float4 w4 = __ldg((const float4*)&g_w[(size_t)row * NBc]);
    int k = threadIdx.x * 4;
    int4 bl = *(const int4*)&g_blk[b * Sc + k];
    float4 o;
    o.x = (k + 0 <= q) ? (bl.x == 0 ? w4.x : bl.x == 1 ? w4.y : bl.x == 2 ? w4.z : w4.w) : 0.f;
    o.y = (k + 1 <= q) ? (bl.y == 0 ? w4.x : bl.y == 1 ? w4.y : bl.y == 2 ? w4.z : w4.w) : 0.f;
    o.z = (k + 2 <= q) ? (bl.z == 0 ? w4.x : bl.z == 1 ? w4.y : bl.z == 2 ? w4.z : w4.w) : 0.f;
    o.w = (k + 3 <= q) ? (bl.w == 0 ? w4.x : bl.w == 1 ? w4.y : bl.w == 2 ? w4.z : w4.w) : 0.f;
    *(float4*)(out + (size_t)row * Sc + k) = o;
}

// ---------------- launch --------------------------------------------------------
extern "C" void kernel_launch(void* const* d_in, const int* in_sizes, int n_in,
                              void* d_out, int out_size) {
    const float* query = (const float*)d_in[0];
    const float* key   = (const float*)d_in[1];
    const float* Wqa   = (const float*)d_in[2];
    const float* Wqb   = (const float*)d_in[3];
    const float* Wka   = (const float*)d_in[4];
    const float* Wkb   = (const float*)d_in[5];
    const float* alpha = (const float*)d_in[6];
    const float* bmask = (const float*)d_in[7];
    float* out = (float*)d_out;

    const int SM_G1 = (3 * 128 * 40 + 3 * 64 * 40) * 2;   // 46080 B
    const int SM_G2 = (3 * 128 * 40 * 2) * 2;             // 61440 B
    const int SM_AT = (128 * 136 + 3 * 64 * 136) * 2;     // 87040 B
    cudaFuncSetAttribute(gemm1_tc, cudaFuncAttributeMaxDynamicSharedMemorySize, SM_G1);
    cudaFuncSetAttribute(gemm2_tc, cudaFuncAttributeMaxDynamicSharedMemorySize, SM_G2);
    cudaFuncSetAttribute(attn_tc,  cudaFuncAttributeMaxDynamicSharedMemorySize, SM_AT);

    prep_kernel<<<Bc, 256>>>(bmask);
    xsplit_kernel<<<dim3(8192, 2), 256>>>(query, key);
    wsplit_kernel<<<dim3(2048, 4), 256>>>(Wqa, Wka, Wqb, Wkb);
    gemm1_tc<<<dim3(LOc / 64, Mc / 128, 4), 256, SM_G1>>>();
    ucomb_kernel<<<dim3(1024, 2), 256>>>();
    gemm2_tc<<<dim3(HIDc / 128, Mc / 128, 2), 256, SM_G2>>>();
    attn_tc<<<dim3(8, Bc * Hc), 256, SM_AT>>>(alpha);
    expand_kernel<<<Bc * Hc * Sc, 256>>>(out);
}